// round 4
// baseline (speedup 1.0000x reference)
#include <cuda_runtime.h>
#include <cuda_bf16.h>

// Problem constants
#define SS   512
#define BB   256
#define DIN  202
#define HH   100
#define TT   19
#define MM   (SS*BB)   // 131072

// ---------------- scratch (device globals; no allocations allowed) ----------
__device__ float g_xp[2ll * SS * BB * HH];     // input projections, both dirs
__device__ float g_h [2ll * SS * BB * HH];     // hidden states, both dirs
__device__ float g_probs[(long long)SS * BB * TT]; // softmax emissions
__device__ float g_res[SS];                    // per-sequence CRF llh

// ---------------- packed f32x2 helpers (FFMA2: ptxas won't emit from C++) ----
typedef unsigned long long u64;

__device__ __forceinline__ float2 upk2(u64 v) {
    float2 f; asm("mov.b64 {%0,%1}, %2;" : "=f"(f.x), "=f"(f.y) : "l"(v)); return f;
}
__device__ __forceinline__ void ffma2(u64& d, u64 a, u64 b) {
    asm("fma.rn.f32x2 %0, %1, %2, %3;" : "=l"(d) : "l"(a), "l"(b), "l"(d));
}

// ---------------------------------------------------------------------------
// K1: input projection  xp[dir][s][b][j] = sum_i x[s][b][i]*W[j][i] + bih[j]+bhh[j]
// 128 rows x 100 cols per CTA; W + x tile in SMEM; 2 rows x 25 cols per thread.
// ---------------------------------------------------------------------------
__global__ void __launch_bounds__(256)
proj_kernel(const float* __restrict__ x,
            const float* __restrict__ Wf,
            const float* __restrict__ Wb,
            const float* __restrict__ bihf,
            const float* __restrict__ bhhf,
            const float* __restrict__ bihb,
            const float* __restrict__ bhhb)
{
    extern __shared__ __align__(16) float sm[];
    float* Ws = sm;              // [100][204]
    float* xs = sm + 100 * 204;  // [128][204]

    const int dir = blockIdx.y;
    const float* W  = dir ? Wb   : Wf;
    const float* bi = dir ? bihb : bihf;
    const float* bh = dir ? bhhb : bhhf;

    const int tid = threadIdx.x;
    const int r0  = blockIdx.x * 128;

    for (int idx = tid; idx < 100 * DIN; idx += 256) {
        int j = idx / DIN, i = idx - j * DIN;
        Ws[j * 204 + i] = W[idx];
    }
    if (tid < 100) { Ws[tid * 204 + 202] = 0.f; Ws[tid * 204 + 203] = 0.f; }

    for (int idx = tid; idx < 128 * DIN; idx += 256) {
        int r = idx / DIN, i = idx - r * DIN;
        xs[r * 204 + i] = x[(size_t)(r0 + r) * DIN + i];
    }
    if (tid < 128) { xs[tid * 204 + 202] = 0.f; xs[tid * 204 + 203] = 0.f; }
    __syncthreads();

    const int rg = tid & 63;        // 64 row-groups (2 rows each)
    const int cg = tid >> 6;        // 4 col-groups (25 cols each)
    const int ra = rg * 2;
    const int j0 = cg * 25;

    u64 acc0[25], acc1[25];
#pragma unroll
    for (int jj = 0; jj < 25; jj++) { acc0[jj] = 0ull; acc1[jj] = 0ull; }

    const ulonglong2* xa8 = (const ulonglong2*)&xs[ ra      * 204];
    const ulonglong2* xb8 = (const ulonglong2*)&xs[(ra + 1) * 204];

    for (int ii = 0; ii < 51; ii++) {
        ulonglong2 xa = xa8[ii];
        ulonglong2 xb = xb8[ii];
#pragma unroll
        for (int jj = 0; jj < 25; jj++) {
            ulonglong2 w = *(const ulonglong2*)&Ws[(j0 + jj) * 204 + ii * 4];
            ffma2(acc0[jj], xa.x, w.x);
            ffma2(acc0[jj], xa.y, w.y);
            ffma2(acc1[jj], xb.x, w.x);
            ffma2(acc1[jj], xb.y, w.y);
        }
    }

#pragma unroll
    for (int jj = 0; jj < 25; jj++) {
        int j = j0 + jj;
        float bias = bi[j] + bh[j];
        float2 a = upk2(acc0[jj]);
        float2 b = upk2(acc1[jj]);
        size_t o = ((size_t)dir * MM + (r0 + ra)) * HH + j;
        g_xp[o]      = a.x + a.y + bias;
        g_xp[o + HH] = b.x + b.y + bias;
    }
}

// ---------------------------------------------------------------------------
// K2: recurrent scan, SPLIT-J version (no spills).
// CTA = (batch b, dir), 256 threads: j = tid>>1 (0..127, act j<100),
// half = tid&1 covers i in [half*50, half*50+50).
// W half-row in 25 u64 REGISTERS (~70 regs total -> 3 CTAs/SM, no spill).
// Partials combined with shfl_xor(1). h reads are 2-address broadcast LDS.
// ---------------------------------------------------------------------------
__global__ void __launch_bounds__(256, 3)
rnn_scan_kernel(const float* __restrict__ Whf,
                const float* __restrict__ Whb)
{
    __shared__ __align__(16) float hbuf[2][104];   // [parity][j]

    const int tid  = threadIdx.x;
    const int b    = blockIdx.x;
    const int dir  = blockIdx.y;
    const int j    = tid >> 1;
    const int half = tid & 1;
    const bool act = (j < 100);
    const int  jc  = act ? j : 0;
    const unsigned FULL = 0xffffffffu;

    // preload this thread's W half-row into registers (25 u64, 8B aligned)
    const float* Wrow = (dir ? Whb : Whf) + jc * HH + half * 50;
    u64 Wp[25];
#pragma unroll
    for (int ii = 0; ii < 25; ii++)
        Wp[ii] = *(const u64*)&Wrow[ii * 2];

    if (tid < 104) { hbuf[0][tid] = 0.f; hbuf[1][tid] = 0.f; }
    __syncthreads();

    // prefetch xp for first step (half 0 only needs it)
    const int s0 = dir ? (SS - 1) : 0;
    float xv = (act && half == 0)
             ? g_xp[(((size_t)dir * SS + s0) * BB + b) * HH + j] : 0.f;

    for (int t = 0; t < SS; t++) {
        int s = dir ? (SS - 1 - t) : t;

        float xnext = 0.f;
        if (t + 1 < SS && act && half == 0) {
            int sn = dir ? (SS - 2 - t) : (t + 1);
            xnext = g_xp[(((size_t)dir * SS + sn) * BB + b) * HH + j];
        }

        const u64* hc = (const u64*)&hbuf[t & 1][half * 50];
        u64 acc0 = 0ull, acc1 = 0ull;
#pragma unroll
        for (int ii = 0; ii < 25; ii += 2) ffma2(acc0, hc[ii], Wp[ii]);
#pragma unroll
        for (int ii = 1; ii < 25; ii += 2) ffma2(acc1, hc[ii], Wp[ii]);

        float2 fa = upk2(acc0);
        float2 fb = upk2(acc1);
        float  sp = (fa.x + fa.y) + (fb.x + fb.y);
        float  so = __shfl_xor_sync(FULL, sp, 1);
        float  z  = xv + sp + so;

        if (act && half == 0) {
            float hn;
            asm("tanh.approx.f32 %0, %1;" : "=f"(hn) : "f"(z));
            hbuf[(t + 1) & 1][j] = hn;
            g_h[(((size_t)dir * SS + s) * BB + b) * HH + j] = hn;
        }
        xv = xnext;
        __syncthreads();
    }
}

// ---------------------------------------------------------------------------
// K3: logits + softmax fused (f32x2 inner product).
// ---------------------------------------------------------------------------
__global__ void __launch_bounds__(128)
logits_softmax_kernel(const float* __restrict__ Wtag,
                      const float* __restrict__ btag)
{
    extern __shared__ __align__(16) float sm[];
    float* Wt2f = sm;           // float2[100][19] -> 3800 floats
    float* hs   = sm + 3800;    // [128][202]

    const int tid  = threadIdx.x;
    const int row0 = blockIdx.x * 128;

    for (int idx = tid; idx < TT * 100; idx += 128) {
        int t = idx / 100, i2 = idx - t * 100;
        Wt2f[(i2 * TT + t) * 2]     = Wtag[t * 200 + 2 * i2];
        Wt2f[(i2 * TT + t) * 2 + 1] = Wtag[t * 200 + 2 * i2 + 1];
    }
    const float* hf = g_h;
    const float* hb = g_h + (size_t)SS * BB * HH;
    for (int idx = tid; idx < 128 * HH; idx += 128) {
        int r = idx / HH, i = idx - r * HH;
        hs[r * 202 + i]       = hf[(size_t)(row0 + r) * HH + i];
        hs[r * 202 + 100 + i] = hb[(size_t)(row0 + r) * HH + i];
    }
    __syncthreads();

    u64 acc[TT];
#pragma unroll
    for (int t = 0; t < TT; t++) acc[t] = 0ull;

    const u64* h2 = (const u64*)&hs[tid * 202];
    for (int i2 = 0; i2 < 100; i2++) {
        u64 hp = h2[i2];
        const u64* wrow = (const u64*)&Wt2f[i2 * TT * 2];
#pragma unroll
        for (int t = 0; t < TT; t++)
            ffma2(acc[t], hp, wrow[t]);
    }

    float lg[TT];
#pragma unroll
    for (int t = 0; t < TT; t++) {
        float2 f = upk2(acc[t]);
        lg[t] = f.x + f.y + btag[t];
    }

    float m = lg[0];
#pragma unroll
    for (int t = 1; t < TT; t++) m = fmaxf(m, lg[t]);
    float sum = 0.f;
#pragma unroll
    for (int t = 0; t < TT; t++) { lg[t] = __expf(lg[t] - m); sum += lg[t]; }
    float inv = 1.0f / sum;

    size_t o = (size_t)(row0 + tid) * TT;
#pragma unroll
    for (int t = 0; t < TT; t++) g_probs[o + t] = lg[t] * inv;
}

// ---------------------------------------------------------------------------
// K4: CRF llh, LINEAR-SPACE forward recursion.
// One warp per sequence. Prologue: exp(em) for all 256 positions -> SMEM
// (parallel), numerator (parallel). Serial loop: p_new = e_em .* (p @ E),
// normalize by z[0] every 4 steps (rcp on critical path, logf on side chain).
// ---------------------------------------------------------------------------
__global__ void __launch_bounds__(32)
crf_kernel(const int* __restrict__ y,
           const float* __restrict__ start_tr,
           const float* __restrict__ end_tr,
           const float* __restrict__ trans)
{
    __shared__ float trans_sh[TT * TT];
    __shared__ float p_sh[32];
    __shared__ float e_em[BB][20];    // exp(emissions), padded stride 20

    const int k = threadIdx.x;
    const int n = blockIdx.x;
    const bool lk = (k < TT);
    const unsigned FULL = 0xffffffffu;

    for (int idx = k; idx < TT * TT; idx += 32) trans_sh[idx] = trans[idx];

    const float* em_base = g_probs + (size_t)n * BB * TT;
    const int*   yrow    = y + (size_t)n * BB;

    // exp(em) prologue (parallel over all 32 lanes)
    for (int idx = k; idx < BB * TT; idx += 32) {
        int l = idx / TT, t = idx - l * TT;
        e_em[l][t] = __expf(em_base[idx]);
    }
    __syncwarp();

    float E[TT];
#pragma unroll
    for (int jj = 0; jj < TT; jj++)
        E[jj] = lk ? __expf(trans_sh[jj * TT + k]) : 0.f;

    // ---- numerator: fully parallel over positions l ----
    float npart = 0.f;
    for (int l = k; l < BB; l += 32) {
        int yl = yrow[l];
        npart += em_base[l * TT + yl];
        if (l + 1 < BB) npart += trans_sh[yl * TT + yrow[l + 1]];
    }
    if (k == 0) npart += start_tr[yrow[0]] + end_tr[yrow[BB - 1]];
#pragma unroll
    for (int off = 16; off; off >>= 1)
        npart += __shfl_xor_sync(FULL, npart, off);
    const float num = npart;

    // ---- forward recursion in linear space ----
    float p    = lk ? __expf(start_tr[k] + em_base[k]) : 0.f;
    float logC = 0.f;

    for (int l = 1; l < BB; l++) {
        p_sh[k] = p;
        __syncwarp();
        float s0 = 0.f, s1 = 0.f, s2 = 0.f, s3 = 0.f;
#pragma unroll
        for (int jj = 0; jj < 5; jj++)  s0 = fmaf(p_sh[jj],      E[jj],      s0);
#pragma unroll
        for (int jj = 0; jj < 5; jj++)  s1 = fmaf(p_sh[5 + jj],  E[5 + jj],  s1);
#pragma unroll
        for (int jj = 0; jj < 5; jj++)  s2 = fmaf(p_sh[10 + jj], E[10 + jj], s2);
#pragma unroll
        for (int jj = 0; jj < 4; jj++)  s3 = fmaf(p_sh[15 + jj], E[15 + jj], s3);
        float d = (s0 + s1) + (s2 + s3);
        float z = lk ? e_em[l][k] * d : 0.f;

        if ((l & 3) == 0) {
            // periodic rescale: divide by z[0]; log goes to a side chain
            float mz = __shfl_sync(FULL, z, 0);
            float r;
            asm("rcp.approx.f32 %0, %1;" : "=f"(r) : "f"(mz));
            p = z * r;
            logC += __logf(mz);
        } else {
            p = z;
        }
        __syncwarp();
    }

    // den = logC + log( sum_k p[k] * exp(end_tr[k]) )
    float term = lk ? p * __expf(end_tr[k]) : 0.f;
#pragma unroll
    for (int off = 16; off; off >>= 1)
        term += __shfl_xor_sync(FULL, term, off);
    float den = logC + __logf(term);

    if (k == 0) g_res[n] = num - den;
}

// ---------------------------------------------------------------------------
// K5: deterministic final reduce of 512 per-sequence results -> scalar
// ---------------------------------------------------------------------------
__global__ void reduce_kernel(float* __restrict__ out)
{
    __shared__ float buf[512];
    int tid = threadIdx.x;
    buf[tid] = g_res[tid];
    __syncthreads();
    for (int s = 256; s > 0; s >>= 1) {
        if (tid < s) buf[tid] += buf[tid + s];
        __syncthreads();
    }
    if (tid == 0) out[0] = buf[0];
}

// ---------------------------------------------------------------------------
extern "C" void kernel_launch(void* const* d_in, const int* in_sizes, int n_in,
                              void* d_out, int out_size)
{
    const float* x        = (const float*)d_in[0];
    const int*   y        = (const int*)d_in[1];      // int32 (JAX default)
    const float* W_ih_f   = (const float*)d_in[2];
    const float* W_hh_f   = (const float*)d_in[3];
    const float* b_ih_f   = (const float*)d_in[4];
    const float* b_hh_f   = (const float*)d_in[5];
    const float* W_ih_b   = (const float*)d_in[6];
    const float* W_hh_b   = (const float*)d_in[7];
    const float* b_ih_b   = (const float*)d_in[8];
    const float* b_hh_b   = (const float*)d_in[9];
    const float* W_tag    = (const float*)d_in[10];
    const float* b_tag    = (const float*)d_in[11];
    const float* start_tr = (const float*)d_in[12];
    const float* end_tr   = (const float*)d_in[13];
    const float* trans    = (const float*)d_in[14];
    float*       out      = (float*)d_out;

    const int proj_smem   = (100 * 204 + 128 * 204) * 4;        // 186048 B
    const int logits_smem = (3800 + 128 * 202) * 4;             // 118624 B
    cudaFuncSetAttribute(proj_kernel,
                         cudaFuncAttributeMaxDynamicSharedMemorySize, proj_smem);
    cudaFuncSetAttribute(logits_softmax_kernel,
                         cudaFuncAttributeMaxDynamicSharedMemorySize, logits_smem);

    proj_kernel<<<dim3(MM / 128, 2), 256, proj_smem>>>(
        x, W_ih_f, W_ih_b, b_ih_f, b_hh_f, b_ih_b, b_hh_b);

    rnn_scan_kernel<<<dim3(BB, 2), 256>>>(W_hh_f, W_hh_b);

    logits_softmax_kernel<<<MM / 128, 128, logits_smem>>>(W_tag, b_tag);

    crf_kernel<<<SS, 32>>>(y, start_tr, end_tr, trans);

    reduce_kernel<<<1, 512>>>(out);
}

// round 5
// speedup vs baseline: 1.0771x; 1.0771x over previous
#include <cuda_runtime.h>
#include <cuda_bf16.h>

// Problem constants
#define SS   512
#define BB   256
#define DIN  202
#define HH   100
#define TT   19
#define MM   (SS*BB)   // 131072

// ---------------- scratch (device globals; no allocations allowed) ----------
__device__ float g_xp[2ll * SS * BB * HH];     // input projections, both dirs
__device__ float g_h [2ll * SS * BB * HH];     // hidden states, both dirs
__device__ float g_probs[(long long)SS * BB * TT]; // softmax emissions
__device__ float g_res[SS];                    // per-sequence CRF llh

// ---------------- packed f32x2 helpers (FFMA2: ptxas won't emit from C++) ----
typedef unsigned long long u64;

__device__ __forceinline__ float2 upk2(u64 v) {
    float2 f; asm("mov.b64 {%0,%1}, %2;" : "=f"(f.x), "=f"(f.y) : "l"(v)); return f;
}
__device__ __forceinline__ void ffma2(u64& d, u64 a, u64 b) {
    asm("fma.rn.f32x2 %0, %1, %2, %3;" : "=l"(d) : "l"(a), "l"(b), "l"(d));
}

// ---------------------------------------------------------------------------
// K1: input projection (unchanged from R3/R4 — at its ffma2 issue floor)
// ---------------------------------------------------------------------------
__global__ void __launch_bounds__(256)
proj_kernel(const float* __restrict__ x,
            const float* __restrict__ Wf,
            const float* __restrict__ Wb,
            const float* __restrict__ bihf,
            const float* __restrict__ bhhf,
            const float* __restrict__ bihb,
            const float* __restrict__ bhhb)
{
    extern __shared__ __align__(16) float sm[];
    float* Ws = sm;              // [100][204]
    float* xs = sm + 100 * 204;  // [128][204]

    const int dir = blockIdx.y;
    const float* W  = dir ? Wb   : Wf;
    const float* bi = dir ? bihb : bihf;
    const float* bh = dir ? bhhb : bhhf;

    const int tid = threadIdx.x;
    const int r0  = blockIdx.x * 128;

    for (int idx = tid; idx < 100 * DIN; idx += 256) {
        int j = idx / DIN, i = idx - j * DIN;
        Ws[j * 204 + i] = W[idx];
    }
    if (tid < 100) { Ws[tid * 204 + 202] = 0.f; Ws[tid * 204 + 203] = 0.f; }

    for (int idx = tid; idx < 128 * DIN; idx += 256) {
        int r = idx / DIN, i = idx - r * DIN;
        xs[r * 204 + i] = x[(size_t)(r0 + r) * DIN + i];
    }
    if (tid < 128) { xs[tid * 204 + 202] = 0.f; xs[tid * 204 + 203] = 0.f; }
    __syncthreads();

    const int rg = tid & 63;
    const int cg = tid >> 6;
    const int ra = rg * 2;
    const int j0 = cg * 25;

    u64 acc0[25], acc1[25];
#pragma unroll
    for (int jj = 0; jj < 25; jj++) { acc0[jj] = 0ull; acc1[jj] = 0ull; }

    const ulonglong2* xa8 = (const ulonglong2*)&xs[ ra      * 204];
    const ulonglong2* xb8 = (const ulonglong2*)&xs[(ra + 1) * 204];

    for (int ii = 0; ii < 51; ii++) {
        ulonglong2 xa = xa8[ii];
        ulonglong2 xb = xb8[ii];
#pragma unroll
        for (int jj = 0; jj < 25; jj++) {
            ulonglong2 w = *(const ulonglong2*)&Ws[(j0 + jj) * 204 + ii * 4];
            ffma2(acc0[jj], xa.x, w.x);
            ffma2(acc0[jj], xa.y, w.y);
            ffma2(acc1[jj], xb.x, w.x);
            ffma2(acc1[jj], xb.y, w.y);
        }
    }

#pragma unroll
    for (int jj = 0; jj < 25; jj++) {
        int j = j0 + jj;
        float bias = bi[j] + bh[j];
        float2 a = upk2(acc0[jj]);
        float2 b = upk2(acc1[jj]);
        size_t o = ((size_t)dir * MM + (r0 + ra)) * HH + j;
        g_xp[o]      = a.x + a.y + bias;
        g_xp[o + HH] = b.x + b.y + bias;
    }
}

// ---------------------------------------------------------------------------
// K2 v5: recurrent scan, split-j + DEEP (8-step) register prefetch of xp.
// CTA = (batch b, dir), 256 threads: j = tid>>1, half = tid&1 (50 i's each).
// W half-row in 25 u64 regs; xp prefetched 8 steps ahead (MLP=8, ~2000 cyc
// slack >> 577 DRAM latency). ~74 regs, no spill at 85-reg cap (occ 3).
// ---------------------------------------------------------------------------
__global__ void __launch_bounds__(256, 3)
rnn_scan_kernel(const float* __restrict__ Whf,
                const float* __restrict__ Whb)
{
    __shared__ __align__(16) float hbuf[2][104];   // [parity][j]

    const int tid  = threadIdx.x;
    const int b    = blockIdx.x;
    const int dir  = blockIdx.y;
    const int j    = tid >> 1;
    const int half = tid & 1;
    const bool act = (j < 100);
    const int  jc  = act ? j : 0;
    const bool ldr = act && (half == 0);   // lanes that own xp/h I/O
    const unsigned FULL = 0xffffffffu;

    // preload this thread's W half-row into registers (25 u64)
    const float* Wrow = (dir ? Whb : Whf) + jc * HH + half * 50;
    u64 Wp[25];
#pragma unroll
    for (int ii = 0; ii < 25; ii++)
        Wp[ii] = *(const u64*)&Wrow[ii * 2];

    if (tid < 104) { hbuf[0][tid] = 0.f; hbuf[1][tid] = 0.f; }

    // xp base for this (dir, b); element (s, j) at  s*BB*HH + j
    const float* xpb = g_xp + ((size_t)dir * SS * BB + b) * HH;
    const int sgn  = dir ? -1 : 1;
    const int base = dir ? (SS - 1) : 0;      // s = base + sgn*t

    // preload xp for steps 0..7
    float xb[8];
#pragma unroll
    for (int q = 0; q < 8; q++)
        xb[q] = ldr ? xpb[(size_t)(base + sgn * q) * (BB * HH) + j] : 0.f;

    __syncthreads();

    for (int t0 = 0; t0 < SS; t0 += 8) {
#pragma unroll
        for (int it = 0; it < 8; it++) {
            const int t = t0 + it;
            const int s = base + sgn * t;

            float xv = xb[it];
            const int tn = t + 8;
            if (tn < SS && ldr)
                xb[it] = xpb[(size_t)(base + sgn * tn) * (BB * HH) + j];

            const u64* hc = (const u64*)&hbuf[t & 1][half * 50];
            u64 acc0 = 0ull, acc1 = 0ull;
#pragma unroll
            for (int ii = 0; ii < 25; ii += 2) ffma2(acc0, hc[ii], Wp[ii]);
#pragma unroll
            for (int ii = 1; ii < 25; ii += 2) ffma2(acc1, hc[ii], Wp[ii]);

            float2 fa = upk2(acc0);
            float2 fb = upk2(acc1);
            float  sp = (fa.x + fa.y) + (fb.x + fb.y);
            float  so = __shfl_xor_sync(FULL, sp, 1);
            float  z  = xv + sp + so;

            if (ldr) {
                float hn;
                asm("tanh.approx.f32 %0, %1;" : "=f"(hn) : "f"(z));
                hbuf[(t + 1) & 1][j] = hn;
                g_h[((size_t)dir * SS * BB + (size_t)s * BB + b) * HH + j] = hn;
            }
            __syncthreads();
        }
    }
}

// ---------------------------------------------------------------------------
// K3: logits + softmax fused (unchanged)
// ---------------------------------------------------------------------------
__global__ void __launch_bounds__(128)
logits_softmax_kernel(const float* __restrict__ Wtag,
                      const float* __restrict__ btag)
{
    extern __shared__ __align__(16) float sm[];
    float* Wt2f = sm;           // float2[100][19] -> 3800 floats
    float* hs   = sm + 3800;    // [128][202]

    const int tid  = threadIdx.x;
    const int row0 = blockIdx.x * 128;

    for (int idx = tid; idx < TT * 100; idx += 128) {
        int t = idx / 100, i2 = idx - t * 100;
        Wt2f[(i2 * TT + t) * 2]     = Wtag[t * 200 + 2 * i2];
        Wt2f[(i2 * TT + t) * 2 + 1] = Wtag[t * 200 + 2 * i2 + 1];
    }
    const float* hf = g_h;
    const float* hb = g_h + (size_t)SS * BB * HH;
    for (int idx = tid; idx < 128 * HH; idx += 128) {
        int r = idx / HH, i = idx - r * HH;
        hs[r * 202 + i]       = hf[(size_t)(row0 + r) * HH + i];
        hs[r * 202 + 100 + i] = hb[(size_t)(row0 + r) * HH + i];
    }
    __syncthreads();

    u64 acc[TT];
#pragma unroll
    for (int t = 0; t < TT; t++) acc[t] = 0ull;

    const u64* h2 = (const u64*)&hs[tid * 202];
    for (int i2 = 0; i2 < 100; i2++) {
        u64 hp = h2[i2];
        const u64* wrow = (const u64*)&Wt2f[i2 * TT * 2];
#pragma unroll
        for (int t = 0; t < TT; t++)
            ffma2(acc[t], hp, wrow[t]);
    }

    float lg[TT];
#pragma unroll
    for (int t = 0; t < TT; t++) {
        float2 f = upk2(acc[t]);
        lg[t] = f.x + f.y + btag[t];
    }

    float m = lg[0];
#pragma unroll
    for (int t = 1; t < TT; t++) m = fmaxf(m, lg[t]);
    float sum = 0.f;
#pragma unroll
    for (int t = 0; t < TT; t++) { lg[t] = __expf(lg[t] - m); sum += lg[t]; }
    float inv = 1.0f / sum;

    size_t o = (size_t)(row0 + tid) * TT;
#pragma unroll
    for (int t = 0; t < TT; t++) g_probs[o + t] = lg[t] * inv;
}

// ---------------------------------------------------------------------------
// K4 v3: CRF llh, linear-space recursion with SHFL-only mat-vec.
// One warp per sequence. Per step: 19 register shfls (no SMEM, no syncwarp)
// + 4-way FMA trees; rescale by lane0 every 4 steps.
// ---------------------------------------------------------------------------
__global__ void __launch_bounds__(32)
crf_kernel(const int* __restrict__ y,
           const float* __restrict__ start_tr,
           const float* __restrict__ end_tr,
           const float* __restrict__ trans)
{
    __shared__ float trans_sh[TT * TT];
    __shared__ float e_em[BB][20];    // exp(emissions), padded stride 20

    const int k = threadIdx.x;
    const int n = blockIdx.x;
    const bool lk = (k < TT);
    const unsigned FULL = 0xffffffffu;

    for (int idx = k; idx < TT * TT; idx += 32) trans_sh[idx] = trans[idx];

    const float* em_base = g_probs + (size_t)n * BB * TT;
    const int*   yrow    = y + (size_t)n * BB;

    // exp(em) prologue (parallel over all 32 lanes)
    for (int idx = k; idx < BB * TT; idx += 32) {
        int l = idx / TT, t = idx - l * TT;
        e_em[l][t] = __expf(em_base[idx]);
    }
    __syncwarp();

    float E[TT];
#pragma unroll
    for (int jj = 0; jj < TT; jj++)
        E[jj] = lk ? __expf(trans_sh[jj * TT + k]) : 0.f;

    // ---- numerator: fully parallel over positions l ----
    float npart = 0.f;
    for (int l = k; l < BB; l += 32) {
        int yl = yrow[l];
        npart += em_base[l * TT + yl];
        if (l + 1 < BB) npart += trans_sh[yl * TT + yrow[l + 1]];
    }
    if (k == 0) npart += start_tr[yrow[0]] + end_tr[yrow[BB - 1]];
#pragma unroll
    for (int off = 16; off; off >>= 1)
        npart += __shfl_xor_sync(FULL, npart, off);
    const float num = npart;

    // ---- forward recursion in linear space, shfl-gathered ----
    float p    = lk ? __expf(start_tr[k] + em_base[k]) : 0.f;
    float logC = 0.f;

    for (int l = 1; l < BB; l++) {
        float s0 = 0.f, s1 = 0.f, s2 = 0.f, s3 = 0.f;
#pragma unroll
        for (int jj = 0; jj < 5; jj++) {
            float pj = __shfl_sync(FULL, p, jj);
            s0 = fmaf(pj, E[jj], s0);
        }
#pragma unroll
        for (int jj = 5; jj < 10; jj++) {
            float pj = __shfl_sync(FULL, p, jj);
            s1 = fmaf(pj, E[jj], s1);
        }
#pragma unroll
        for (int jj = 10; jj < 15; jj++) {
            float pj = __shfl_sync(FULL, p, jj);
            s2 = fmaf(pj, E[jj], s2);
        }
#pragma unroll
        for (int jj = 15; jj < 19; jj++) {
            float pj = __shfl_sync(FULL, p, jj);
            s3 = fmaf(pj, E[jj], s3);
        }
        float d = (s0 + s1) + (s2 + s3);
        float z = lk ? e_em[l][k] * d : 0.f;

        if ((l & 3) == 0) {
            float mz = __shfl_sync(FULL, z, 0);
            float r;
            asm("rcp.approx.f32 %0, %1;" : "=f"(r) : "f"(mz));
            p = z * r;
            logC += __logf(mz);
        } else {
            p = z;
        }
    }

    // den = logC + log( sum_k p[k] * exp(end_tr[k]) )
    float term = lk ? p * __expf(end_tr[k]) : 0.f;
#pragma unroll
    for (int off = 16; off; off >>= 1)
        term += __shfl_xor_sync(FULL, term, off);
    float den = logC + __logf(term);

    if (k == 0) g_res[n] = num - den;
}

// ---------------------------------------------------------------------------
// K5: deterministic final reduce
// ---------------------------------------------------------------------------
__global__ void reduce_kernel(float* __restrict__ out)
{
    __shared__ float buf[512];
    int tid = threadIdx.x;
    buf[tid] = g_res[tid];
    __syncthreads();
    for (int s = 256; s > 0; s >>= 1) {
        if (tid < s) buf[tid] += buf[tid + s];
        __syncthreads();
    }
    if (tid == 0) out[0] = buf[0];
}

// ---------------------------------------------------------------------------
extern "C" void kernel_launch(void* const* d_in, const int* in_sizes, int n_in,
                              void* d_out, int out_size)
{
    const float* x        = (const float*)d_in[0];
    const int*   y        = (const int*)d_in[1];      // int32 (JAX default)
    const float* W_ih_f   = (const float*)d_in[2];
    const float* W_hh_f   = (const float*)d_in[3];
    const float* b_ih_f   = (const float*)d_in[4];
    const float* b_hh_f   = (const float*)d_in[5];
    const float* W_ih_b   = (const float*)d_in[6];
    const float* W_hh_b   = (const float*)d_in[7];
    const float* b_ih_b   = (const float*)d_in[8];
    const float* b_hh_b   = (const float*)d_in[9];
    const float* W_tag    = (const float*)d_in[10];
    const float* b_tag    = (const float*)d_in[11];
    const float* start_tr = (const float*)d_in[12];
    const float* end_tr   = (const float*)d_in[13];
    const float* trans    = (const float*)d_in[14];
    float*       out      = (float*)d_out;

    const int proj_smem   = (100 * 204 + 128 * 204) * 4;        // 186048 B
    const int logits_smem = (3800 + 128 * 202) * 4;             // 118624 B
    cudaFuncSetAttribute(proj_kernel,
                         cudaFuncAttributeMaxDynamicSharedMemorySize, proj_smem);
    cudaFuncSetAttribute(logits_softmax_kernel,
                         cudaFuncAttributeMaxDynamicSharedMemorySize, logits_smem);

    proj_kernel<<<dim3(MM / 128, 2), 256, proj_smem>>>(
        x, W_ih_f, W_ih_b, b_ih_f, b_hh_f, b_ih_b, b_hh_b);

    rnn_scan_kernel<<<dim3(BB, 2), 256>>>(W_hh_f, W_hh_b);

    logits_softmax_kernel<<<MM / 128, 128, logits_smem>>>(W_tag, b_tag);

    crf_kernel<<<SS, 32>>>(y, start_tr, end_tr, trans);

    reduce_kernel<<<1, 512>>>(out);
}

// round 7
// speedup vs baseline: 1.9471x; 1.8077x over previous
#include <cuda_runtime.h>
#include <cuda_bf16.h>
#include <cstdint>

// Problem constants
#define SS   512
#define BB   256
#define DIN  202
#define HH   100
#define TT   19
#define MM   (SS*BB)   // 131072

// ---------------- scratch (device globals; no allocations allowed) ----------
__device__ float g_xp[2ll * SS * BB * HH];     // input projections, both dirs
__device__ float g_h [2ll * SS * BB * HH];     // hidden states, both dirs
__device__ float g_probs[(long long)SS * BB * TT]; // softmax emissions
__device__ float g_res[SS];                    // per-sequence CRF llh

// ---------------- packed f32x2 helpers ----------
typedef unsigned long long u64;

__device__ __forceinline__ u64 pk2(float lo, float hi) {
    u64 r; asm("mov.b64 %0, {%1,%2};" : "=l"(r) : "f"(lo), "f"(hi)); return r;
}
__device__ __forceinline__ float2 upk2(u64 v) {
    float2 f; asm("mov.b64 {%0,%1}, %2;" : "=f"(f.x), "=f"(f.y) : "l"(v)); return f;
}
__device__ __forceinline__ void ffma2(u64& d, u64 a, u64 b) {
    asm("fma.rn.f32x2 %0, %1, %2, %3;" : "=l"(d) : "l"(a), "l"(b), "l"(d));
}

__device__ __forceinline__ uint32_t smem_u32(const void* p) {
    uint32_t a;
    asm("{ .reg .u64 t; cvta.to.shared.u64 t, %1; cvt.u32.u64 %0, t; }"
        : "=r"(a) : "l"(p));
    return a;
}

// bf16x2 pack
__device__ __forceinline__ uint32_t bf16x2(float lo, float hi) {
    uint32_t l = (uint32_t)__bfloat16_as_ushort(__float2bfloat16_rn(lo));
    uint32_t h = (uint32_t)__bfloat16_as_ushort(__float2bfloat16_rn(hi));
    return l | (h << 16);
}

// ---------------------------------------------------------------------------
// K1 (mma.sync bf16): xp = x @ W^T + bias.
// Per CTA: M=128 (8 warps x m16), N=104 (13 n8-tiles, 100 real),
// K=208 (13 k16-tiles, 202 real). SMEM row stride 216 bf16 = 432 B
// (conflict-free ldmatrix: r*12 mod 32 distinct over 8 rows).
// ---------------------------------------------------------------------------
#define K1_STRIDE 216                       // bf16 per SMEM row
#define K1_A_BYTES (128 * K1_STRIDE * 2)    // 55296
#define K1_B_BYTES (112 * K1_STRIDE * 2)    // 48384 (rows 100..111 zero pad)
#define K1_BIAS_OFF (K1_A_BYTES + K1_B_BYTES)
#define K1_SMEM (K1_BIAS_OFF + 104 * 4)     // 104096

__device__ __forceinline__ void ldsm_x4(uint32_t a[4], uint32_t addr) {
    asm volatile("ldmatrix.sync.aligned.m8n8.x4.shared.b16 {%0,%1,%2,%3}, [%4];"
                 : "=r"(a[0]), "=r"(a[1]), "=r"(a[2]), "=r"(a[3]) : "r"(addr));
}
__device__ __forceinline__ void ldsm_x2(uint32_t a[2], uint32_t addr) {
    asm volatile("ldmatrix.sync.aligned.m8n8.x2.shared.b16 {%0,%1}, [%2];"
                 : "=r"(a[0]), "=r"(a[1]) : "r"(addr));
}
__device__ __forceinline__ void mma_bf16(float c[4], const uint32_t a[4],
                                         uint32_t b0, uint32_t b1) {
    asm volatile("mma.sync.aligned.m16n8k16.row.col.f32.bf16.bf16.f32 "
                 "{%0,%1,%2,%3}, {%4,%5,%6,%7}, {%8,%9}, {%0,%1,%2,%3};"
                 : "+f"(c[0]), "+f"(c[1]), "+f"(c[2]), "+f"(c[3])
                 : "r"(a[0]), "r"(a[1]), "r"(a[2]), "r"(a[3]),
                   "r"(b0), "r"(b1));
}

__global__ void proj_mma_kernel(const float* __restrict__ x,
                                const float* __restrict__ Wf,
                                const float* __restrict__ Wb,
                                const float* __restrict__ bihf,
                                const float* __restrict__ bhhf,
                                const float* __restrict__ bihb,
                                const float* __restrict__ bhhb)
{
    extern __shared__ __align__(16) char smem[];
    const uint32_t sbase = smem_u32(smem);
    float* bias_sh = (float*)(smem + K1_BIAS_OFF);

    const int tid = threadIdx.x;            // 256 threads = 8 warps
    const int wid = tid >> 5;
    const int lane = tid & 31;
    const int dir = blockIdx.y;
    const int r0  = blockIdx.x * 128;

    const float* W  = dir ? Wb   : Wf;
    const float* bi = dir ? bihb : bihf;
    const float* bh = dir ? bhhb : bhhf;

    if (tid < 104) bias_sh[tid] = (tid < HH) ? (bi[tid] + bh[tid]) : 0.f;

    // ---- fill A: x[r0..r0+127][0..207] -> bf16, stride 216 ----
    for (int idx = tid; idx < 128 * 104; idx += 256) {
        int r = idx / 104, kp = idx - r * 104, k = kp * 2;
        float2 xv = make_float2(0.f, 0.f);
        if (k < DIN) xv = *(const float2*)&x[(size_t)(r0 + r) * DIN + k];
        *(uint32_t*)(smem + r * (K1_STRIDE * 2) + kp * 4) = bf16x2(xv.x, xv.y);
    }
    // ---- fill B: W[j][k] (n-major, k contiguous), rows 100..111 zero ----
    for (int idx = tid; idx < 112 * 104; idx += 256) {
        int j = idx / 104, kp = idx - j * 104, k = kp * 2;
        float2 wv = make_float2(0.f, 0.f);
        if (j < HH && k < DIN) wv = *(const float2*)&W[(size_t)j * DIN + k];
        *(uint32_t*)(smem + K1_A_BYTES + j * (K1_STRIDE * 2) + kp * 4) =
            bf16x2(wv.x, wv.y);
    }
    __syncthreads();

    const int m0 = wid * 16;
    float acc[13][4];
#pragma unroll
    for (int nt = 0; nt < 13; nt++)
#pragma unroll
        for (int c = 0; c < 4; c++) acc[nt][c] = 0.f;

    const uint32_t sA = sbase;
    const uint32_t sB = sbase + K1_A_BYTES;

#pragma unroll
    for (int kt = 0; kt < 13; kt++) {
        // A fragment: rows m0+(lane&15), k-chunk (lane>>4)*16B
        uint32_t a[4];
        ldsm_x4(a, sA + (uint32_t)((m0 + (lane & 15)) * 432 + kt * 32
                                   + (lane >> 4) * 16));
        // B tiles in pairs: lane groups of 8 -> (tile, khalf)
#pragma unroll
        for (int ntp = 0; ntp < 6; ntp++) {
            uint32_t b[4];
            int tile = 2 * ntp + (lane >> 4);
            int row  = tile * 8 + (lane & 7);
            ldsm_x4(b, sB + (uint32_t)(row * 432 + kt * 32
                                       + ((lane >> 3) & 1) * 16));
            mma_bf16(acc[2 * ntp],     a, b[0], b[1]);
            mma_bf16(acc[2 * ntp + 1], a, b[2], b[3]);
        }
        {   // last tile (12) alone
            uint32_t b[2];
            int row = 12 * 8 + (lane & 7);
            ldsm_x2(b, sB + (uint32_t)(row * 432 + kt * 32
                                       + ((lane >> 3) & 1) * 16));
            mma_bf16(acc[12], a, b[0], b[1]);
        }
    }

    // ---- epilogue: c frag lane layout: rows m0+lane/4 (+8), cols (lane&3)*2 ----
    const int rowA = m0 + (lane >> 2);
    const int rowB = rowA + 8;
    float* dA = &g_xp[((size_t)dir * MM + r0 + rowA) * HH];
    float* dB = &g_xp[((size_t)dir * MM + r0 + rowB) * HH];
#pragma unroll
    for (int nt = 0; nt < 13; nt++) {
        int col = nt * 8 + (lane & 3) * 2;
        if (col < HH) {
            float b0 = bias_sh[col], b1 = bias_sh[col + 1];
            *(float2*)&dA[col] = make_float2(acc[nt][0] + b0, acc[nt][1] + b1);
            *(float2*)&dB[col] = make_float2(acc[nt][2] + b0, acc[nt][3] + b1);
        }
    }
}

// ---------------------------------------------------------------------------
// K2 v7: split-j scan, occ 4 (single wave), xp staged via cp.async (no relay
// registers -> fits 64-reg cap). 8-step double-buffered SMEM stage.
// ---------------------------------------------------------------------------
__device__ __forceinline__ void cp_async4(uint32_t dst, const float* src) {
    asm volatile("cp.async.ca.shared.global [%0], [%1], 4;"
                 :: "r"(dst), "l"(src) : "memory");
}

__global__ void __launch_bounds__(256, 4)
rnn_scan_kernel(const float* __restrict__ Whf,
                const float* __restrict__ Whb)
{
    __shared__ __align__(16) float hbuf[2][104];
    __shared__ __align__(16) float xstage[2][8][104];

    const int tid  = threadIdx.x;
    const int b    = blockIdx.x;
    const int dir  = blockIdx.y;
    const int j    = tid >> 1;
    const int half = tid & 1;
    const bool act = (j < 100);
    const int  jc  = act ? j : 0;
    const bool ldr = act && (half == 0);
    const unsigned FULL = 0xffffffffu;

    const float* Wrow = (dir ? Whb : Whf) + jc * HH + half * 50;
    u64 Wp[25];
#pragma unroll
    for (int ii = 0; ii < 25; ii++)
        Wp[ii] = *(const u64*)&Wrow[ii * 2];

    if (tid < 104) { hbuf[0][tid] = 0.f; hbuf[1][tid] = 0.f; }

    const int BHH  = BB * HH;
    const float* xpb = g_xp + (size_t)dir * SS * BHH + (size_t)b * HH;
    const int sgn  = dir ? -1 : 1;
    const int base = dir ? (SS - 1) : 0;

    // prefill stage buffer 0 with steps 0..7 (plain loads)
    for (int idx = tid; idx < 800; idx += 256) {
        int q = idx / 100, i = idx - q * 100;
        xstage[0][q][i] = xpb[(size_t)(base + sgn * q) * BHH + i];
    }
    __syncthreads();

    for (int t0 = 0; t0 < SS; t0 += 8) {
        const int buf = (t0 >> 3) & 1;

        // issue async prefetch of steps t0+8..t0+15 into buf^1
        if (t0 + 8 < SS) {
            int sb = t0 + 8;
            for (int idx = tid; idx < 800; idx += 256) {
                int q = idx / 100, i = idx - q * 100;
                cp_async4(smem_u32(&xstage[buf ^ 1][q][i]),
                          &xpb[(size_t)(base + sgn * (sb + q)) * BHH + i]);
            }
        }
        asm volatile("cp.async.commit_group;" ::: "memory");

#pragma unroll
        for (int it = 0; it < 8; it++) {
            const int t = t0 + it;

            float xv = xstage[buf][it][jc];

            const u64* hc = (const u64*)&hbuf[t & 1][half * 50];
            u64 acc0 = 0ull, acc1 = 0ull;
#pragma unroll
            for (int ii = 0; ii < 25; ii += 2) ffma2(acc0, hc[ii], Wp[ii]);
#pragma unroll
            for (int ii = 1; ii < 25; ii += 2) ffma2(acc1, hc[ii], Wp[ii]);

            float2 fa = upk2(acc0);
            float2 fb = upk2(acc1);
            float  sp = (fa.x + fa.y) + (fb.x + fb.y);
            float  so = __shfl_xor_sync(FULL, sp, 1);
            float  z  = xv + sp + so;

            if (ldr) {
                const int s = base + sgn * t;
                float hn;
                asm("tanh.approx.f32 %0, %1;" : "=f"(hn) : "f"(z));
                hbuf[(t + 1) & 1][j] = hn;
                g_h[(size_t)dir * SS * BHH + (size_t)s * BHH
                    + (size_t)b * HH + j] = hn;
            }
            if (it == 7)
                asm volatile("cp.async.wait_group 0;" ::: "memory");
            __syncthreads();
        }
    }
}

// ---------------------------------------------------------------------------
// K3: logits + softmax fused (R5-proven version; f32x2 inner product)
// ---------------------------------------------------------------------------
__global__ void __launch_bounds__(128)
logits_softmax_kernel(const float* __restrict__ Wtag,
                      const float* __restrict__ btag)
{
    extern __shared__ __align__(16) float sm3[];
    float* Wt2f = sm3;           // float2[100][19] -> 3800 floats
    float* hs   = sm3 + 3800;    // [128][202]

    const int tid  = threadIdx.x;
    const int row0 = blockIdx.x * 128;

    for (int idx = tid; idx < TT * 100; idx += 128) {
        int t = idx / 100, i2 = idx - t * 100;
        Wt2f[(i2 * TT + t) * 2]     = Wtag[t * 200 + 2 * i2];
        Wt2f[(i2 * TT + t) * 2 + 1] = Wtag[t * 200 + 2 * i2 + 1];
    }
    const float* hf = g_h;
    const float* hb = g_h + (size_t)SS * BB * HH;
    for (int idx = tid; idx < 128 * HH; idx += 128) {
        int r = idx / HH, i = idx - r * HH;
        hs[r * 202 + i]       = hf[(size_t)(row0 + r) * HH + i];
        hs[r * 202 + 100 + i] = hb[(size_t)(row0 + r) * HH + i];
    }
    __syncthreads();

    u64 acc[TT];
#pragma unroll
    for (int t = 0; t < TT; t++) acc[t] = 0ull;

    const u64* h2 = (const u64*)&hs[tid * 202];
    for (int i2 = 0; i2 < 100; i2++) {
        u64 hp = h2[i2];
        const u64* wrow = (const u64*)&Wt2f[i2 * TT * 2];
#pragma unroll
        for (int t = 0; t < TT; t++)
            ffma2(acc[t], hp, wrow[t]);
    }

    float lg[TT];
#pragma unroll
    for (int t = 0; t < TT; t++) {
        float2 f = upk2(acc[t]);
        lg[t] = f.x + f.y + btag[t];
    }

    float m = lg[0];
#pragma unroll
    for (int t = 1; t < TT; t++) m = fmaxf(m, lg[t]);
    float sum = 0.f;
#pragma unroll
    for (int t = 0; t < TT; t++) { lg[t] = __expf(lg[t] - m); sum += lg[t]; }
    float inv = 1.0f / sum;

    size_t o = (size_t)(row0 + tid) * TT;
#pragma unroll
    for (int t = 0; t < TT; t++) g_probs[o + t] = lg[t] * inv;
}

// ---------------------------------------------------------------------------
// K4: CRF llh (R5-proven; shfl-gathered linear-space recursion)
// ---------------------------------------------------------------------------
__global__ void __launch_bounds__(32)
crf_kernel(const int* __restrict__ y,
           const float* __restrict__ start_tr,
           const float* __restrict__ end_tr,
           const float* __restrict__ trans)
{
    __shared__ float trans_sh[TT * TT];
    __shared__ float e_em[BB][20];

    const int k = threadIdx.x;
    const int n = blockIdx.x;
    const bool lk = (k < TT);
    const unsigned FULL = 0xffffffffu;

    for (int idx = k; idx < TT * TT; idx += 32) trans_sh[idx] = trans[idx];

    const float* em_base = g_probs + (size_t)n * BB * TT;
    const int*   yrow    = y + (size_t)n * BB;

    for (int idx = k; idx < BB * TT; idx += 32) {
        int l = idx / TT, t = idx - l * TT;
        e_em[l][t] = __expf(em_base[idx]);
    }
    __syncwarp();

    float E[TT];
#pragma unroll
    for (int jj = 0; jj < TT; jj++)
        E[jj] = lk ? __expf(trans_sh[jj * TT + k]) : 0.f;

    float npart = 0.f;
    for (int l = k; l < BB; l += 32) {
        int yl = yrow[l];
        npart += em_base[l * TT + yl];
        if (l + 1 < BB) npart += trans_sh[yl * TT + yrow[l + 1]];
    }
    if (k == 0) npart += start_tr[yrow[0]] + end_tr[yrow[BB - 1]];
#pragma unroll
    for (int off = 16; off; off >>= 1)
        npart += __shfl_xor_sync(FULL, npart, off);
    const float num = npart;

    float p    = lk ? __expf(start_tr[k] + em_base[k]) : 0.f;
    float logC = 0.f;

    for (int l = 1; l < BB; l++) {
        float s0 = 0.f, s1 = 0.f, s2 = 0.f, s3 = 0.f;
#pragma unroll
        for (int jj = 0; jj < 5; jj++) {
            float pj = __shfl_sync(FULL, p, jj);
            s0 = fmaf(pj, E[jj], s0);
        }
#pragma unroll
        for (int jj = 5; jj < 10; jj++) {
            float pj = __shfl_sync(FULL, p, jj);
            s1 = fmaf(pj, E[jj], s1);
        }
#pragma unroll
        for (int jj = 10; jj < 15; jj++) {
            float pj = __shfl_sync(FULL, p, jj);
            s2 = fmaf(pj, E[jj], s2);
        }
#pragma unroll
        for (int jj = 15; jj < 19; jj++) {
            float pj = __shfl_sync(FULL, p, jj);
            s3 = fmaf(pj, E[jj], s3);
        }
        float d = (s0 + s1) + (s2 + s3);
        float z = lk ? e_em[l][k] * d : 0.f;

        if ((l & 3) == 0) {
            float mz = __shfl_sync(FULL, z, 0);
            float r;
            asm("rcp.approx.f32 %0, %1;" : "=f"(r) : "f"(mz));
            p = z * r;
            logC += __logf(mz);
        } else {
            p = z;
        }
    }

    float term = lk ? p * __expf(end_tr[k]) : 0.f;
#pragma unroll
    for (int off = 16; off; off >>= 1)
        term += __shfl_xor_sync(FULL, term, off);
    float den = logC + __logf(term);

    if (k == 0) g_res[n] = num - den;
}

// ---------------------------------------------------------------------------
// K5: deterministic final reduce
// ---------------------------------------------------------------------------
__global__ void reduce_kernel(float* __restrict__ out)
{
    __shared__ float buf[512];
    int tid = threadIdx.x;
    buf[tid] = g_res[tid];
    __syncthreads();
    for (int s = 256; s > 0; s >>= 1) {
        if (tid < s) buf[tid] += buf[tid + s];
        __syncthreads();
    }
    if (tid == 0) out[0] = buf[0];
}

// ---------------------------------------------------------------------------
extern "C" void kernel_launch(void* const* d_in, const int* in_sizes, int n_in,
                              void* d_out, int out_size)
{
    const float* x        = (const float*)d_in[0];
    const int*   y        = (const int*)d_in[1];
    const float* W_ih_f   = (const float*)d_in[2];
    const float* W_hh_f   = (const float*)d_in[3];
    const float* b_ih_f   = (const float*)d_in[4];
    const float* b_hh_f   = (const float*)d_in[5];
    const float* W_ih_b   = (const float*)d_in[6];
    const float* W_hh_b   = (const float*)d_in[7];
    const float* b_ih_b   = (const float*)d_in[8];
    const float* b_hh_b   = (const float*)d_in[9];
    const float* W_tag    = (const float*)d_in[10];
    const float* b_tag    = (const float*)d_in[11];
    const float* start_tr = (const float*)d_in[12];
    const float* end_tr   = (const float*)d_in[13];
    const float* trans    = (const float*)d_in[14];
    float*       out      = (float*)d_out;

    const int logits_smem = (3800 + 128 * 202) * 4;   // 118624 B
    cudaFuncSetAttribute(proj_mma_kernel,
                         cudaFuncAttributeMaxDynamicSharedMemorySize, K1_SMEM);
    cudaFuncSetAttribute(logits_softmax_kernel,
                         cudaFuncAttributeMaxDynamicSharedMemorySize, logits_smem);

    proj_mma_kernel<<<dim3(MM / 128, 2), 256, K1_SMEM>>>(
        x, W_ih_f, W_ih_b, b_ih_f, b_hh_f, b_ih_b, b_hh_b);

    rnn_scan_kernel<<<dim3(BB, 2), 256>>>(W_hh_f, W_hh_b);

    logits_softmax_kernel<<<MM / 128, 128, logits_smem>>>(W_tag, b_tag);

    crf_kernel<<<SS, 32>>>(y, start_tr, end_tr, trans);

    reduce_kernel<<<1, 512>>>(out);
}

// round 8
// speedup vs baseline: 2.0067x; 1.0306x over previous
#include <cuda_runtime.h>
#include <cuda_bf16.h>
#include <cstdint>

// Problem constants
#define SS   512
#define BB   256
#define DIN  202
#define HH   100
#define TT   19
#define MM   (SS*BB)   // 131072

// ---------------- scratch (device globals; no allocations allowed) ----------
__device__ uint32_t g_xp_bf[2ll * SS * BB * 50];        // bf16x2-packed xp
__device__ __nv_bfloat16 g_h_bf[2ll * SS * BB * HH];    // bf16 hidden states
__device__ float g_probs[(long long)SS * BB * TT];      // softmax emissions
__device__ float g_res[SS];                             // per-sequence CRF llh

// ---------------- packed f32x2 helpers ----------
typedef unsigned long long u64;

__device__ __forceinline__ u64 pk2(float lo, float hi) {
    u64 r; asm("mov.b64 %0, {%1,%2};" : "=l"(r) : "f"(lo), "f"(hi)); return r;
}
__device__ __forceinline__ float2 upk2(u64 v) {
    float2 f; asm("mov.b64 {%0,%1}, %2;" : "=f"(f.x), "=f"(f.y) : "l"(v)); return f;
}
__device__ __forceinline__ void ffma2(u64& d, u64 a, u64 b) {
    asm("fma.rn.f32x2 %0, %1, %2, %3;" : "=l"(d) : "l"(a), "l"(b), "l"(d));
}

__device__ __forceinline__ uint32_t smem_u32(const void* p) {
    uint32_t a;
    asm("{ .reg .u64 t; cvta.to.shared.u64 t, %1; cvt.u32.u64 %0, t; }"
        : "=r"(a) : "l"(p));
    return a;
}

__device__ __forceinline__ uint32_t bf16x2(float lo, float hi) {
    uint32_t l = (uint32_t)__bfloat16_as_ushort(__float2bfloat16_rn(lo));
    uint32_t h = (uint32_t)__bfloat16_as_ushort(__float2bfloat16_rn(hi));
    return l | (h << 16);
}

// ---------------------------------------------------------------------------
// K1 (mma.sync bf16, BOTH dirs fused): xp[dir] = x @ W[dir]^T + bias[dir].
// Per CTA: M=128 rows, N=2x104 (2x100 real), K=208 (13 k16-tiles, 202 real).
// x tile read ONCE for both dirs. Output packed bf16x2.
// SMEM stride 216 bf16 = 432 B (conflict-free ldmatrix).
// ---------------------------------------------------------------------------
#define K1_STRIDE 216
#define K1_A_BYTES (128 * K1_STRIDE * 2)      // 55296
#define K1_B_BYTES (224 * K1_STRIDE * 2)      // 96768 (112 rows per dir)
#define K1_BIAS_OFF (K1_A_BYTES + K1_B_BYTES) // 152064
#define K1_SMEM (K1_BIAS_OFF + 208 * 4)       // 152896

__device__ __forceinline__ void ldsm_x4(uint32_t a[4], uint32_t addr) {
    asm volatile("ldmatrix.sync.aligned.m8n8.x4.shared.b16 {%0,%1,%2,%3}, [%4];"
                 : "=r"(a[0]), "=r"(a[1]), "=r"(a[2]), "=r"(a[3]) : "r"(addr));
}
__device__ __forceinline__ void ldsm_x2(uint32_t a[2], uint32_t addr) {
    asm volatile("ldmatrix.sync.aligned.m8n8.x2.shared.b16 {%0,%1}, [%2];"
                 : "=r"(a[0]), "=r"(a[1]) : "r"(addr));
}
__device__ __forceinline__ void mma_bf16(float c[4], const uint32_t a[4],
                                         uint32_t b0, uint32_t b1) {
    asm volatile("mma.sync.aligned.m16n8k16.row.col.f32.bf16.bf16.f32 "
                 "{%0,%1,%2,%3}, {%4,%5,%6,%7}, {%8,%9}, {%0,%1,%2,%3};"
                 : "+f"(c[0]), "+f"(c[1]), "+f"(c[2]), "+f"(c[3])
                 : "r"(a[0]), "r"(a[1]), "r"(a[2]), "r"(a[3]),
                   "r"(b0), "r"(b1));
}

__global__ void proj_mma_kernel(const float* __restrict__ x,
                                const float* __restrict__ Wf,
                                const float* __restrict__ Wb,
                                const float* __restrict__ bihf,
                                const float* __restrict__ bhhf,
                                const float* __restrict__ bihb,
                                const float* __restrict__ bhhb)
{
    extern __shared__ __align__(16) char smem[];
    const uint32_t sbase = smem_u32(smem);
    float* bias_sh = (float*)(smem + K1_BIAS_OFF);   // [2][104]

    const int tid = threadIdx.x;            // 256 threads = 8 warps
    const int wid = tid >> 5;
    const int lane = tid & 31;
    const int r0  = blockIdx.x * 128;

    if (tid < 208) {
        int d = tid >= 104, jj = tid - d * 104;
        const float* bi = d ? bihb : bihf;
        const float* bh = d ? bhhb : bhhf;
        bias_sh[tid] = (jj < HH) ? (bi[jj] + bh[jj]) : 0.f;
    }

    // ---- fill A: x[r0..r0+127][0..207] -> bf16, stride 216 ----
    for (int idx = tid; idx < 128 * 104; idx += 256) {
        int r = idx / 104, kp = idx - r * 104, k = kp * 2;
        float2 xv = make_float2(0.f, 0.f);
        if (k < DIN) xv = *(const float2*)&x[(size_t)(r0 + r) * DIN + k];
        *(uint32_t*)(smem + r * 432 + kp * 4) = bf16x2(xv.x, xv.y);
    }
    // ---- fill B: rows 0..111 = Wf, 112..223 = Wb (each padded to 112) ----
    for (int idx = tid; idx < 224 * 104; idx += 256) {
        int j = idx / 104, kp = idx - j * 104, k = kp * 2;
        int d = j >= 112, jj = j - d * 112;
        const float* W = d ? Wb : Wf;
        float2 wv = make_float2(0.f, 0.f);
        if (jj < HH && k < DIN) wv = *(const float2*)&W[(size_t)jj * DIN + k];
        *(uint32_t*)(smem + K1_A_BYTES + j * 432 + kp * 4) = bf16x2(wv.x, wv.y);
    }
    __syncthreads();

    const int m0 = wid * 16;
    float accA[13][4], accB[13][4];
#pragma unroll
    for (int nt = 0; nt < 13; nt++)
#pragma unroll
        for (int c = 0; c < 4; c++) { accA[nt][c] = 0.f; accB[nt][c] = 0.f; }

    const uint32_t sA = sbase;
    const uint32_t sB = sbase + K1_A_BYTES;

    for (int kt = 0; kt < 13; kt++) {
        uint32_t a[4];
        ldsm_x4(a, sA + (uint32_t)((m0 + (lane & 15)) * 432 + kt * 32
                                   + (lane >> 4) * 16));
#pragma unroll
        for (int ntp = 0; ntp < 6; ntp++) {
            uint32_t b[4];
            int tile = 2 * ntp + (lane >> 4);
            // dir 0
            ldsm_x4(b, sB + (uint32_t)((tile * 8 + (lane & 7)) * 432 + kt * 32
                                       + ((lane >> 3) & 1) * 16));
            mma_bf16(accA[2 * ntp],     a, b[0], b[1]);
            mma_bf16(accA[2 * ntp + 1], a, b[2], b[3]);
            // dir 1 (rows +112)
            ldsm_x4(b, sB + (uint32_t)(((112 + tile * 8) + (lane & 7)) * 432
                                       + kt * 32 + ((lane >> 3) & 1) * 16));
            mma_bf16(accB[2 * ntp],     a, b[0], b[1]);
            mma_bf16(accB[2 * ntp + 1], a, b[2], b[3]);
        }
        {   // tile 12, both dirs
            uint32_t b[2];
            ldsm_x2(b, sB + (uint32_t)((96 + (lane & 7)) * 432 + kt * 32
                                       + ((lane >> 3) & 1) * 16));
            mma_bf16(accA[12], a, b[0], b[1]);
            ldsm_x2(b, sB + (uint32_t)((208 + (lane & 7)) * 432 + kt * 32
                                       + ((lane >> 3) & 1) * 16));
            mma_bf16(accB[12], a, b[0], b[1]);
        }
    }

    // ---- epilogue: pack bf16x2 pairs; rows m0+lane/4 and +8 ----
    const int rowA = r0 + m0 + (lane >> 2);
    const int rowB = rowA + 8;
    uint32_t* d0A = &g_xp_bf[(size_t)rowA * 50];
    uint32_t* d0B = &g_xp_bf[(size_t)rowB * 50];
    uint32_t* d1A = &g_xp_bf[(size_t)MM * 50 + (size_t)rowA * 50];
    uint32_t* d1B = &g_xp_bf[(size_t)MM * 50 + (size_t)rowB * 50];
#pragma unroll
    for (int nt = 0; nt < 13; nt++) {
        int col = nt * 8 + (lane & 3) * 2;
        if (col < HH) {
            float b00 = bias_sh[col], b01 = bias_sh[col + 1];
            float b10 = bias_sh[104 + col], b11 = bias_sh[104 + col + 1];
            d0A[col >> 1] = bf16x2(accA[nt][0] + b00, accA[nt][1] + b01);
            d0B[col >> 1] = bf16x2(accA[nt][2] + b00, accA[nt][3] + b01);
            d1A[col >> 1] = bf16x2(accB[nt][0] + b10, accB[nt][1] + b11);
            d1B[col >> 1] = bf16x2(accB[nt][2] + b10, accB[nt][3] + b11);
        }
    }
}

// ---------------------------------------------------------------------------
// K2: split-j scan, occ 4, xp staged via cp.async from bf16x2-packed g_xp_bf.
// h written as bf16.
// ---------------------------------------------------------------------------
__device__ __forceinline__ void cp_async4(uint32_t dst, const void* src) {
    asm volatile("cp.async.ca.shared.global [%0], [%1], 4;"
                 :: "r"(dst), "l"(src) : "memory");
}

__global__ void __launch_bounds__(256, 4)
rnn_scan_kernel(const float* __restrict__ Whf,
                const float* __restrict__ Whb)
{
    __shared__ __align__(16) float hbuf[2][104];
    __shared__ __align__(16) uint32_t xstage[2][8][52];

    const int tid  = threadIdx.x;
    const int b    = blockIdx.x;
    const int dir  = blockIdx.y;
    const int j    = tid >> 1;
    const int half = tid & 1;
    const bool act = (j < 100);
    const int  jc  = act ? j : 0;
    const bool ldr = act && (half == 0);
    const unsigned FULL = 0xffffffffu;

    const float* Wrow = (dir ? Whb : Whf) + jc * HH + half * 50;
    u64 Wp[25];
#pragma unroll
    for (int ii = 0; ii < 25; ii++)
        Wp[ii] = *(const u64*)&Wrow[ii * 2];

    if (tid < 104) { hbuf[0][tid] = 0.f; hbuf[1][tid] = 0.f; }

    const int BHH = BB * HH;
    const uint32_t* xpb = g_xp_bf + (size_t)dir * SS * BB * 50 + (size_t)b * 50;
    const int sgn  = dir ? -1 : 1;
    const int base = dir ? (SS - 1) : 0;

    // prefill stage buffer 0 with steps 0..7
    for (int idx = tid; idx < 400; idx += 256) {
        int q = idx / 50, i = idx - q * 50;
        xstage[0][q][i] = xpb[(size_t)(base + sgn * q) * (BB * 50) + i];
    }
    __syncthreads();

    for (int t0 = 0; t0 < SS; t0 += 8) {
        const int buf = (t0 >> 3) & 1;

        if (t0 + 8 < SS) {
            int sb = t0 + 8;
            for (int idx = tid; idx < 400; idx += 256) {
                int q = idx / 50, i = idx - q * 50;
                cp_async4(smem_u32(&xstage[buf ^ 1][q][i]),
                          &xpb[(size_t)(base + sgn * (sb + q)) * (BB * 50) + i]);
            }
        }
        asm volatile("cp.async.commit_group;" ::: "memory");

#pragma unroll
        for (int it = 0; it < 8; it++) {
            const int t = t0 + it;

            uint32_t up = xstage[buf][it][jc >> 1];
            float xv = __uint_as_float((jc & 1) ? (up & 0xffff0000u)
                                                : (up << 16));

            const u64* hc = (const u64*)&hbuf[t & 1][half * 50];
            u64 acc0 = 0ull, acc1 = 0ull;
#pragma unroll
            for (int ii = 0; ii < 25; ii += 2) ffma2(acc0, hc[ii], Wp[ii]);
#pragma unroll
            for (int ii = 1; ii < 25; ii += 2) ffma2(acc1, hc[ii], Wp[ii]);

            float2 fa = upk2(acc0);
            float2 fb = upk2(acc1);
            float  sp = (fa.x + fa.y) + (fb.x + fb.y);
            float  so = __shfl_xor_sync(FULL, sp, 1);
            float  z  = xv + sp + so;

            if (ldr) {
                const int s = base + sgn * t;
                float hn;
                asm("tanh.approx.f32 %0, %1;" : "=f"(hn) : "f"(z));
                hbuf[(t + 1) & 1][j] = hn;
                g_h_bf[(size_t)dir * SS * BHH + (size_t)s * BHH
                       + (size_t)b * HH + j] = __float2bfloat16_rn(hn);
            }
            if (it == 7)
                asm volatile("cp.async.wait_group 0;" ::: "memory");
            __syncthreads();
        }
    }
}

// ---------------------------------------------------------------------------
// K3: logits + softmax fused (bf16 h input, f32x2 inner product)
// ---------------------------------------------------------------------------
__global__ void __launch_bounds__(128)
logits_softmax_kernel(const float* __restrict__ Wtag,
                      const float* __restrict__ btag)
{
    extern __shared__ __align__(16) float sm3[];
    float* Wt2f = sm3;           // float2[100][19] -> 3800 floats
    float* hs   = sm3 + 3800;    // [128][202]

    const int tid  = threadIdx.x;
    const int row0 = blockIdx.x * 128;

    for (int idx = tid; idx < TT * 100; idx += 128) {
        int t = idx / 100, i2 = idx - t * 100;
        Wt2f[(i2 * TT + t) * 2]     = Wtag[t * 200 + 2 * i2];
        Wt2f[(i2 * TT + t) * 2 + 1] = Wtag[t * 200 + 2 * i2 + 1];
    }
    const __nv_bfloat16* hf = g_h_bf;
    const __nv_bfloat16* hb = g_h_bf + (size_t)SS * BB * HH;
    for (int idx = tid; idx < 128 * HH; idx += 128) {
        int r = idx / HH, i = idx - r * HH;
        hs[r * 202 + i]       = __bfloat162float(hf[(size_t)(row0 + r) * HH + i]);
        hs[r * 202 + 100 + i] = __bfloat162float(hb[(size_t)(row0 + r) * HH + i]);
    }
    __syncthreads();

    u64 acc[TT];
#pragma unroll
    for (int t = 0; t < TT; t++) acc[t] = 0ull;

    const u64* h2 = (const u64*)&hs[tid * 202];
    for (int i2 = 0; i2 < 100; i2++) {
        u64 hp = h2[i2];
        const u64* wrow = (const u64*)&Wt2f[i2 * TT * 2];
#pragma unroll
        for (int t = 0; t < TT; t++)
            ffma2(acc[t], hp, wrow[t]);
    }

    float lg[TT];
#pragma unroll
    for (int t = 0; t < TT; t++) {
        float2 f = upk2(acc[t]);
        lg[t] = f.x + f.y + btag[t];
    }

    float m = lg[0];
#pragma unroll
    for (int t = 1; t < TT; t++) m = fmaxf(m, lg[t]);
    float sum = 0.f;
#pragma unroll
    for (int t = 0; t < TT; t++) { lg[t] = __expf(lg[t] - m); sum += lg[t]; }
    float inv = 1.0f / sum;

    size_t o = (size_t)(row0 + tid) * TT;
#pragma unroll
    for (int t = 0; t < TT; t++) g_probs[o + t] = lg[t] * inv;
}

// ---------------------------------------------------------------------------
// K4: CRF llh (unchanged; shfl-gathered linear-space recursion)
// ---------------------------------------------------------------------------
__global__ void __launch_bounds__(32)
crf_kernel(const int* __restrict__ y,
           const float* __restrict__ start_tr,
           const float* __restrict__ end_tr,
           const float* __restrict__ trans)
{
    __shared__ float trans_sh[TT * TT];
    __shared__ float e_em[BB][20];

    const int k = threadIdx.x;
    const int n = blockIdx.x;
    const bool lk = (k < TT);
    const unsigned FULL = 0xffffffffu;

    for (int idx = k; idx < TT * TT; idx += 32) trans_sh[idx] = trans[idx];

    const float* em_base = g_probs + (size_t)n * BB * TT;
    const int*   yrow    = y + (size_t)n * BB;

    for (int idx = k; idx < BB * TT; idx += 32) {
        int l = idx / TT, t = idx - l * TT;
        e_em[l][t] = __expf(em_base[idx]);
    }
    __syncwarp();

    float E[TT];
#pragma unroll
    for (int jj = 0; jj < TT; jj++)
        E[jj] = lk ? __expf(trans_sh[jj * TT + k]) : 0.f;

    float npart = 0.f;
    for (int l = k; l < BB; l += 32) {
        int yl = yrow[l];
        npart += em_base[l * TT + yl];
        if (l + 1 < BB) npart += trans_sh[yl * TT + yrow[l + 1]];
    }
    if (k == 0) npart += start_tr[yrow[0]] + end_tr[yrow[BB - 1]];
#pragma unroll
    for (int off = 16; off; off >>= 1)
        npart += __shfl_xor_sync(FULL, npart, off);
    const float num = npart;

    float p    = lk ? __expf(start_tr[k] + em_base[k]) : 0.f;
    float logC = 0.f;

    for (int l = 1; l < BB; l++) {
        float s0 = 0.f, s1 = 0.f, s2 = 0.f, s3 = 0.f;
#pragma unroll
        for (int jj = 0; jj < 5; jj++) {
            float pj = __shfl_sync(FULL, p, jj);
            s0 = fmaf(pj, E[jj], s0);
        }
#pragma unroll
        for (int jj = 5; jj < 10; jj++) {
            float pj = __shfl_sync(FULL, p, jj);
            s1 = fmaf(pj, E[jj], s1);
        }
#pragma unroll
        for (int jj = 10; jj < 15; jj++) {
            float pj = __shfl_sync(FULL, p, jj);
            s2 = fmaf(pj, E[jj], s2);
        }
#pragma unroll
        for (int jj = 15; jj < 19; jj++) {
            float pj = __shfl_sync(FULL, p, jj);
            s3 = fmaf(pj, E[jj], s3);
        }
        float d = (s0 + s1) + (s2 + s3);
        float z = lk ? e_em[l][k] * d : 0.f;

        if ((l & 3) == 0) {
            float mz = __shfl_sync(FULL, z, 0);
            float r;
            asm("rcp.approx.f32 %0, %1;" : "=f"(r) : "f"(mz));
            p = z * r;
            logC += __logf(mz);
        } else {
            p = z;
        }
    }

    float term = lk ? p * __expf(end_tr[k]) : 0.f;
#pragma unroll
    for (int off = 16; off; off >>= 1)
        term += __shfl_xor_sync(FULL, term, off);
    float den = logC + __logf(term);

    if (k == 0) g_res[n] = num - den;
}

// ---------------------------------------------------------------------------
// K5: deterministic final reduce
// ---------------------------------------------------------------------------
__global__ void reduce_kernel(float* __restrict__ out)
{
    __shared__ float buf[512];
    int tid = threadIdx.x;
    buf[tid] = g_res[tid];
    __syncthreads();
    for (int s = 256; s > 0; s >>= 1) {
        if (tid < s) buf[tid] += buf[tid + s];
        __syncthreads();
    }
    if (tid == 0) out[0] = buf[0];
}

// ---------------------------------------------------------------------------
extern "C" void kernel_launch(void* const* d_in, const int* in_sizes, int n_in,
                              void* d_out, int out_size)
{
    const float* x        = (const float*)d_in[0];
    const int*   y        = (const int*)d_in[1];
    const float* W_ih_f   = (const float*)d_in[2];
    const float* W_hh_f   = (const float*)d_in[3];
    const float* b_ih_f   = (const float*)d_in[4];
    const float* b_hh_f   = (const float*)d_in[5];
    const float* W_ih_b   = (const float*)d_in[6];
    const float* W_hh_b   = (const float*)d_in[7];
    const float* b_ih_b   = (const float*)d_in[8];
    const float* b_hh_b   = (const float*)d_in[9];
    const float* W_tag    = (const float*)d_in[10];
    const float* b_tag    = (const float*)d_in[11];
    const float* start_tr = (const float*)d_in[12];
    const float* end_tr   = (const float*)d_in[13];
    const float* trans    = (const float*)d_in[14];
    float*       out      = (float*)d_out;

    const int logits_smem = (3800 + 128 * 202) * 4;   // 118624 B
    cudaFuncSetAttribute(proj_mma_kernel,
                         cudaFuncAttributeMaxDynamicSharedMemorySize, K1_SMEM);
    cudaFuncSetAttribute(logits_softmax_kernel,
                         cudaFuncAttributeMaxDynamicSharedMemorySize, logits_smem);

    proj_mma_kernel<<<MM / 128, 256, K1_SMEM>>>(
        x, W_ih_f, W_ih_b, b_ih_f, b_hh_f, b_ih_b, b_hh_b);

    rnn_scan_kernel<<<dim3(BB, 2), 256>>>(W_hh_f, W_hh_b);

    logits_softmax_kernel<<<MM / 128, 128, logits_smem>>>(W_tag, b_tag);

    crf_kernel<<<SS, 32>>>(y, start_tr, end_tr, trans);

    reduce_kernel<<<1, 512>>>(out);
}

// round 10
// speedup vs baseline: 2.4182x; 1.2051x over previous
#include <cuda_runtime.h>
#include <cuda_bf16.h>
#include <cstdint>

// Problem constants
#define SS   512
#define BB   256
#define DIN  202
#define HH   100
#define TT   19
#define MM   (SS*BB)   // 131072

// ---------------- scratch (device globals; no allocations allowed) ----------
__device__ uint32_t g_xp_bf[2ll * SS * BB * 50];   // bf16x2-packed xp
__device__ uint32_t g_h_pk[2ll * SS * BB * 50];    // bf16x2-packed hidden
__device__ float g_probs[(long long)SS * BB * TT]; // softmax emissions
__device__ float g_res[SS];                        // per-sequence CRF llh

// ---------------- helpers ----------
typedef unsigned long long u64;

__device__ __forceinline__ u64 pk2(float lo, float hi) {
    u64 r; asm("mov.b64 %0, {%1,%2};" : "=l"(r) : "f"(lo), "f"(hi)); return r;
}
__device__ __forceinline__ float2 upk2(u64 v) {
    float2 f; asm("mov.b64 {%0,%1}, %2;" : "=f"(f.x), "=f"(f.y) : "l"(v)); return f;
}
__device__ __forceinline__ void ffma2(u64& d, u64 a, u64 b) {
    asm("fma.rn.f32x2 %0, %1, %2, %3;" : "=l"(d) : "l"(a), "l"(b), "l"(d));
}
__device__ __forceinline__ uint32_t smem_u32(const void* p) {
    uint32_t a;
    asm("{ .reg .u64 t; cvta.to.shared.u64 t, %1; cvt.u32.u64 %0, t; }"
        : "=r"(a) : "l"(p));
    return a;
}
__device__ __forceinline__ uint32_t bf16x2(float lo, float hi) {
    uint32_t l = (uint32_t)__bfloat16_as_ushort(__float2bfloat16_rn(lo));
    uint32_t h = (uint32_t)__bfloat16_as_ushort(__float2bfloat16_rn(hi));
    return l | (h << 16);
}
__device__ __forceinline__ uint32_t bfpack2(float lo, float hi) {
    uint32_t r;
    asm("cvt.rn.bf16x2.f32 %0, %1, %2;" : "=r"(r) : "f"(hi), "f"(lo));
    return r;
}
__device__ __forceinline__ float bflo(uint32_t u) {
    return __uint_as_float(u << 16);
}
__device__ __forceinline__ float bfhi(uint32_t u) {
    return __uint_as_float(u & 0xffff0000u);
}

__device__ __forceinline__ void ldsm_x4(uint32_t a[4], uint32_t addr) {
    asm volatile("ldmatrix.sync.aligned.m8n8.x4.shared.b16 {%0,%1,%2,%3}, [%4];"
                 : "=r"(a[0]), "=r"(a[1]), "=r"(a[2]), "=r"(a[3]) : "r"(addr));
}
__device__ __forceinline__ void ldsm_x2(uint32_t a[2], uint32_t addr) {
    asm volatile("ldmatrix.sync.aligned.m8n8.x2.shared.b16 {%0,%1}, [%2];"
                 : "=r"(a[0]), "=r"(a[1]) : "r"(addr));
}
__device__ __forceinline__ void mma_bf16(float c[4], const uint32_t a[4],
                                         uint32_t b0, uint32_t b1) {
    asm volatile("mma.sync.aligned.m16n8k16.row.col.f32.bf16.bf16.f32 "
                 "{%0,%1,%2,%3}, {%4,%5,%6,%7}, {%8,%9}, {%0,%1,%2,%3};"
                 : "+f"(c[0]), "+f"(c[1]), "+f"(c[2]), "+f"(c[3])
                 : "r"(a[0]), "r"(a[1]), "r"(a[2]), "r"(a[3]),
                   "r"(b0), "r"(b1));
}
__device__ __forceinline__ void cp_async16(uint32_t dst, const void* src) {
    asm volatile("cp.async.cg.shared.global [%0], [%1], 16;"
                 :: "r"(dst), "l"(src) : "memory");
}

// ---------------------------------------------------------------------------
// K1 (mma.sync bf16, BOTH dirs fused) — unchanged (passing since R8).
// ---------------------------------------------------------------------------
#define K1_STRIDE 216
#define K1_A_BYTES (128 * K1_STRIDE * 2)
#define K1_B_BYTES (224 * K1_STRIDE * 2)
#define K1_BIAS_OFF (K1_A_BYTES + K1_B_BYTES)
#define K1_SMEM (K1_BIAS_OFF + 208 * 4)

__global__ void proj_mma_kernel(const float* __restrict__ x,
                                const float* __restrict__ Wf,
                                const float* __restrict__ Wb,
                                const float* __restrict__ bihf,
                                const float* __restrict__ bhhf,
                                const float* __restrict__ bihb,
                                const float* __restrict__ bhhb)
{
    extern __shared__ __align__(16) char smem[];
    const uint32_t sbase = smem_u32(smem);
    float* bias_sh = (float*)(smem + K1_BIAS_OFF);

    const int tid = threadIdx.x;
    const int wid = tid >> 5;
    const int lane = tid & 31;
    const int r0  = blockIdx.x * 128;

    if (tid < 208) {
        int d = tid >= 104, jj = tid - d * 104;
        const float* bi = d ? bihb : bihf;
        const float* bh = d ? bhhb : bhhf;
        bias_sh[tid] = (jj < HH) ? (bi[jj] + bh[jj]) : 0.f;
    }

    for (int idx = tid; idx < 128 * 104; idx += 256) {
        int r = idx / 104, kp = idx - r * 104, k = kp * 2;
        float2 xv = make_float2(0.f, 0.f);
        if (k < DIN) xv = *(const float2*)&x[(size_t)(r0 + r) * DIN + k];
        *(uint32_t*)(smem + r * 432 + kp * 4) = bf16x2(xv.x, xv.y);
    }
    for (int idx = tid; idx < 224 * 104; idx += 256) {
        int j = idx / 104, kp = idx - j * 104, k = kp * 2;
        int d = j >= 112, jj = j - d * 112;
        const float* W = d ? Wb : Wf;
        float2 wv = make_float2(0.f, 0.f);
        if (jj < HH && k < DIN) wv = *(const float2*)&W[(size_t)jj * DIN + k];
        *(uint32_t*)(smem + K1_A_BYTES + j * 432 + kp * 4) = bf16x2(wv.x, wv.y);
    }
    __syncthreads();

    const int m0 = wid * 16;
    float accA[13][4], accB[13][4];
#pragma unroll
    for (int nt = 0; nt < 13; nt++)
#pragma unroll
        for (int c = 0; c < 4; c++) { accA[nt][c] = 0.f; accB[nt][c] = 0.f; }

    const uint32_t sA = sbase;
    const uint32_t sB = sbase + K1_A_BYTES;

    for (int kt = 0; kt < 13; kt++) {
        uint32_t a[4];
        ldsm_x4(a, sA + (uint32_t)((m0 + (lane & 15)) * 432 + kt * 32
                                   + (lane >> 4) * 16));
#pragma unroll
        for (int ntp = 0; ntp < 6; ntp++) {
            uint32_t b[4];
            int tile = 2 * ntp + (lane >> 4);
            ldsm_x4(b, sB + (uint32_t)((tile * 8 + (lane & 7)) * 432 + kt * 32
                                       + ((lane >> 3) & 1) * 16));
            mma_bf16(accA[2 * ntp],     a, b[0], b[1]);
            mma_bf16(accA[2 * ntp + 1], a, b[2], b[3]);
            ldsm_x4(b, sB + (uint32_t)(((112 + tile * 8) + (lane & 7)) * 432
                                       + kt * 32 + ((lane >> 3) & 1) * 16));
            mma_bf16(accB[2 * ntp],     a, b[0], b[1]);
            mma_bf16(accB[2 * ntp + 1], a, b[2], b[3]);
        }
        {
            uint32_t b[2];
            ldsm_x2(b, sB + (uint32_t)((96 + (lane & 7)) * 432 + kt * 32
                                       + ((lane >> 3) & 1) * 16));
            mma_bf16(accA[12], a, b[0], b[1]);
            ldsm_x2(b, sB + (uint32_t)((208 + (lane & 7)) * 432 + kt * 32
                                       + ((lane >> 3) & 1) * 16));
            mma_bf16(accB[12], a, b[0], b[1]);
        }
    }

    const int rowA = r0 + m0 + (lane >> 2);
    const int rowB = rowA + 8;
    uint32_t* d0A = &g_xp_bf[(size_t)rowA * 50];
    uint32_t* d0B = &g_xp_bf[(size_t)rowB * 50];
    uint32_t* d1A = &g_xp_bf[(size_t)MM * 50 + (size_t)rowA * 50];
    uint32_t* d1B = &g_xp_bf[(size_t)MM * 50 + (size_t)rowB * 50];
#pragma unroll
    for (int nt = 0; nt < 13; nt++) {
        int col = nt * 8 + (lane & 3) * 2;
        if (col < HH) {
            float b00 = bias_sh[col], b01 = bias_sh[col + 1];
            float b10 = bias_sh[104 + col], b11 = bias_sh[104 + col + 1];
            d0A[col >> 1] = bf16x2(accA[nt][0] + b00, accA[nt][1] + b01);
            d0B[col >> 1] = bf16x2(accA[nt][2] + b00, accA[nt][3] + b01);
            d1A[col >> 1] = bf16x2(accB[nt][0] + b10, accB[nt][1] + b11);
            d1B[col >> 1] = bf16x2(accB[nt][2] + b10, accB[nt][3] + b11);
        }
    }
}

// ---------------------------------------------------------------------------
// K2 (mma.sync recurrent scan): one CTA = 16 sequences of one direction.
// Per step: h_t[16x100] = tanh( h_{t-1}[16x100] @ W_hh^T + xp_t ), bf16
// tensor-core, W_hh fragments register-resident, h double-buffered in SMEM,
// xp streamed via 16B cp.async.
// FIX vs R9: SMEM row stride 240 B (multiple of 16 — ldmatrix requires 16B-
// aligned row addresses; 232 trapped with misaligned address).
// Bank phases r*60 mod 32 = {0,28,24,20,16,12,8,4} -> conflict-free.
// ---------------------------------------------------------------------------
#define K2_STRIDE 240                // bytes per row (120 bf16, k-pad zeroed)
#define K2_OFF_B 0                   // W_hh: 104 x 240 = 24960
#define K2_OFF_A 24960               // h: 2 x 16 x 240 = 7680
#define K2_OFF_X 32640               // xp: 2 x 8 x 3200 = 51200
#define K2_SMEM  (32640 + 51200)     // 83840

__global__ void __launch_bounds__(256)
rnn_scan_mma_kernel(const float* __restrict__ Whf,
                    const float* __restrict__ Whb)
{
    extern __shared__ __align__(16) char sm2[];
    const uint32_t sbase = smem_u32(sm2);
    uint32_t* xs = (uint32_t*)(sm2 + K2_OFF_X);

    const int tid  = threadIdx.x;
    const int w    = tid >> 5;
    const int lane = tid & 31;
    const int dir  = blockIdx.y;
    const int b0   = blockIdx.x * 16;
    const float* Whh = dir ? Whb : Whf;

    // ---- fill B = W_hh[j][i] bf16 (rows pad 100..103, k pad 100..119) ----
    for (int idx = tid; idx < 104 * 60; idx += 256) {
        int j = idx / 60, kp = idx - j * 60, k = kp * 2;
        float w0 = 0.f, w1 = 0.f;
        if (j < HH && k < HH) { w0 = Whh[j * HH + k]; w1 = Whh[j * HH + k + 1]; }
        *(uint32_t*)(sm2 + K2_OFF_B + j * K2_STRIDE + kp * 4) = bf16x2(w0, w1);
    }
    // ---- zero h (both buffers incl. k-pad): 2*16*240 B = 1920 words ----
    for (int idx = tid; idx < 1920; idx += 256)
        ((uint32_t*)(sm2 + K2_OFF_A))[idx] = 0u;

    // ---- prefill xp stage 0 with steps 0..7 ----
    const uint32_t* xpg = g_xp_bf + (size_t)dir * SS * BB * 50;
    const int base = dir ? (SS - 1) : 0;
    const int sgn  = dir ? -1 : 1;
    for (int q = 0; q < 8; q++) {
        const uint32_t* src = xpg + (size_t)(base + sgn * q) * (BB * 50) + b0 * 50;
        for (int idx = tid; idx < 800; idx += 256)
            xs[q * 800 + idx] = src[idx];
    }
    __syncthreads();

    // ---- preload W_hh fragments into registers (once) ----
    uint32_t Bf[7][4];
    if (w < 6) {
#pragma unroll
        for (int kt = 0; kt < 7; kt++)
            ldsm_x4(Bf[kt], sbase + K2_OFF_B
                    + (uint32_t)(((2 * w + (lane >> 4)) * 8 + (lane & 7)) * K2_STRIDE
                                 + kt * 32 + ((lane >> 3) & 1) * 16));
    } else if (w == 6) {
#pragma unroll
        for (int kt = 0; kt < 7; kt++)
            ldsm_x2(Bf[kt], sbase + K2_OFF_B
                    + (uint32_t)((96 + (lane & 7)) * K2_STRIDE
                                 + kt * 32 + ((lane >> 3) & 1) * 16));
    }

    const int rowA = lane >> 2;
    const int rowB = rowA + 8;

    for (int t0 = 0; t0 < SS; t0 += 8) {
        const int buf = (t0 >> 3) & 1;

        // async prefetch next 8 steps (16B ops; per-step chunk contiguous)
        if (t0 + 8 < SS && tid < 200) {
#pragma unroll
            for (int q = 0; q < 8; q++) {
                const char* src = (const char*)(xpg
                    + (size_t)(base + sgn * (t0 + 8 + q)) * (BB * 50) + b0 * 50);
                cp_async16(sbase + K2_OFF_X + (buf ^ 1) * 25600 + q * 3200
                           + tid * 16, src + tid * 16);
            }
        }
        asm volatile("cp.async.commit_group;" ::: "memory");

        for (int it = 0; it < 8; it++) {
            const int t = t0 + it;
            const int cur = t & 1, nxt = cur ^ 1;

            if (w < 7) {
                float c0e[4] = {0,0,0,0}, c0o[4] = {0,0,0,0};
                float c1e[4] = {0,0,0,0}, c1o[4] = {0,0,0,0};
#pragma unroll
                for (int kt = 0; kt < 7; kt++) {
                    uint32_t a[4];
                    ldsm_x4(a, sbase + K2_OFF_A
                            + (uint32_t)(cur * 3840 + (lane & 15) * K2_STRIDE
                                         + kt * 32 + (lane >> 4) * 16));
                    float* c0 = (kt & 1) ? c0o : c0e;
                    mma_bf16(c0, a, Bf[kt][0], Bf[kt][1]);
                    if (w < 6) {
                        float* c1 = (kt & 1) ? c1o : c1e;
                        mma_bf16(c1, a, Bf[kt][2], Bf[kt][3]);
                    }
                }
                const int s = base + sgn * t;
                const uint32_t* xrow = &xs[buf * 6400 + it * 800];
                const size_t gb = ((size_t)dir * SS + s) * (BB * 50);

                // tile nt0
                {
                    int nt = (w < 6) ? 2 * w : 12;
                    int col = nt * 8 + (lane & 3) * 2;
                    uint32_t pA = xrow[rowA * 50 + (col >> 1)];
                    uint32_t pB = xrow[rowB * 50 + (col >> 1)];
                    float z0 = c0e[0] + c0o[0] + bflo(pA);
                    float z1 = c0e[1] + c0o[1] + bfhi(pA);
                    float z2 = c0e[2] + c0o[2] + bflo(pB);
                    float z3 = c0e[3] + c0o[3] + bfhi(pB);
                    float h0, h1, h2, h3;
                    asm("tanh.approx.f32 %0, %1;" : "=f"(h0) : "f"(z0));
                    asm("tanh.approx.f32 %0, %1;" : "=f"(h1) : "f"(z1));
                    asm("tanh.approx.f32 %0, %1;" : "=f"(h2) : "f"(z2));
                    asm("tanh.approx.f32 %0, %1;" : "=f"(h3) : "f"(z3));
                    uint32_t hA = bfpack2(h0, h1), hB = bfpack2(h2, h3);
                    if (col < HH) {
                        *(uint32_t*)(sm2 + K2_OFF_A + nxt * 3840
                                     + rowA * K2_STRIDE + col * 2) = hA;
                        *(uint32_t*)(sm2 + K2_OFF_A + nxt * 3840
                                     + rowB * K2_STRIDE + col * 2) = hB;
                        g_h_pk[gb + (b0 + rowA) * 50 + (col >> 1)] = hA;
                        g_h_pk[gb + (b0 + rowB) * 50 + (col >> 1)] = hB;
                    }
                }
                // tile nt1 (warps 0-5 only); cols always < 100
                if (w < 6) {
                    int col = (2 * w + 1) * 8 + (lane & 3) * 2;
                    uint32_t pA = xrow[rowA * 50 + (col >> 1)];
                    uint32_t pB = xrow[rowB * 50 + (col >> 1)];
                    float z0 = c1e[0] + c1o[0] + bflo(pA);
                    float z1 = c1e[1] + c1o[1] + bfhi(pA);
                    float z2 = c1e[2] + c1o[2] + bflo(pB);
                    float z3 = c1e[3] + c1o[3] + bfhi(pB);
                    float h0, h1, h2, h3;
                    asm("tanh.approx.f32 %0, %1;" : "=f"(h0) : "f"(z0));
                    asm("tanh.approx.f32 %0, %1;" : "=f"(h1) : "f"(z1));
                    asm("tanh.approx.f32 %0, %1;" : "=f"(h2) : "f"(z2));
                    asm("tanh.approx.f32 %0, %1;" : "=f"(h3) : "f"(z3));
                    uint32_t hA = bfpack2(h0, h1), hB = bfpack2(h2, h3);
                    *(uint32_t*)(sm2 + K2_OFF_A + nxt * 3840
                                 + rowA * K2_STRIDE + col * 2) = hA;
                    *(uint32_t*)(sm2 + K2_OFF_A + nxt * 3840
                                 + rowB * K2_STRIDE + col * 2) = hB;
                    g_h_pk[gb + (b0 + rowA) * 50 + (col >> 1)] = hA;
                    g_h_pk[gb + (b0 + rowB) * 50 + (col >> 1)] = hB;
                }
            }
            if (it == 7)
                asm volatile("cp.async.wait_group 0;" ::: "memory");
            __syncthreads();
        }
    }
}

// ---------------------------------------------------------------------------
// K3: logits + softmax fused (reads packed bf16x2 h)
// ---------------------------------------------------------------------------
__global__ void __launch_bounds__(128)
logits_softmax_kernel(const float* __restrict__ Wtag,
                      const float* __restrict__ btag)
{
    extern __shared__ __align__(16) float sm3[];
    float* Wt2f = sm3;           // float2[100][19] -> 3800 floats
    float* hs   = sm3 + 3800;    // [128][202]

    const int tid  = threadIdx.x;
    const int row0 = blockIdx.x * 128;

    for (int idx = tid; idx < TT * 100; idx += 128) {
        int t = idx / 100, i2 = idx - t * 100;
        Wt2f[(i2 * TT + t) * 2]     = Wtag[t * 200 + 2 * i2];
        Wt2f[(i2 * TT + t) * 2 + 1] = Wtag[t * 200 + 2 * i2 + 1];
    }
    const uint32_t* hf = g_h_pk;
    const uint32_t* hb = g_h_pk + (size_t)MM * 50;
    for (int idx = tid; idx < 128 * 50; idx += 128) {
        int r = idx / 50, i2 = idx - r * 50;
        uint32_t v0 = hf[(size_t)(row0 + r) * 50 + i2];
        uint32_t v1 = hb[(size_t)(row0 + r) * 50 + i2];
        hs[r * 202 + 2 * i2]           = bflo(v0);
        hs[r * 202 + 2 * i2 + 1]       = bfhi(v0);
        hs[r * 202 + 100 + 2 * i2]     = bflo(v1);
        hs[r * 202 + 100 + 2 * i2 + 1] = bfhi(v1);
    }
    __syncthreads();

    u64 acc[TT];
#pragma unroll
    for (int t = 0; t < TT; t++) acc[t] = 0ull;

    const u64* h2 = (const u64*)&hs[tid * 202];
    for (int i2 = 0; i2 < 100; i2++) {
        u64 hp = h2[i2];
        const u64* wrow = (const u64*)&Wt2f[i2 * TT * 2];
#pragma unroll
        for (int t = 0; t < TT; t++)
            ffma2(acc[t], hp, wrow[t]);
    }

    float lg[TT];
#pragma unroll
    for (int t = 0; t < TT; t++) {
        float2 f = upk2(acc[t]);
        lg[t] = f.x + f.y + btag[t];
    }

    float m = lg[0];
#pragma unroll
    for (int t = 1; t < TT; t++) m = fmaxf(m, lg[t]);
    float sum = 0.f;
#pragma unroll
    for (int t = 0; t < TT; t++) { lg[t] = __expf(lg[t] - m); sum += lg[t]; }
    float inv = 1.0f / sum;

    size_t o = (size_t)(row0 + tid) * TT;
#pragma unroll
    for (int t = 0; t < TT; t++) g_probs[o + t] = lg[t] * inv;
}

// ---------------------------------------------------------------------------
// K4: CRF llh (unchanged)
// ---------------------------------------------------------------------------
__global__ void __launch_bounds__(32)
crf_kernel(const int* __restrict__ y,
           const float* __restrict__ start_tr,
           const float* __restrict__ end_tr,
           const float* __restrict__ trans)
{
    __shared__ float trans_sh[TT * TT];
    __shared__ float e_em[BB][20];

    const int k = threadIdx.x;
    const int n = blockIdx.x;
    const bool lk = (k < TT);
    const unsigned FULL = 0xffffffffu;

    for (int idx = k; idx < TT * TT; idx += 32) trans_sh[idx] = trans[idx];

    const float* em_base = g_probs + (size_t)n * BB * TT;
    const int*   yrow    = y + (size_t)n * BB;

    for (int idx = k; idx < BB * TT; idx += 32) {
        int l = idx / TT, t = idx - l * TT;
        e_em[l][t] = __expf(em_base[idx]);
    }
    __syncwarp();

    float E[TT];
#pragma unroll
    for (int jj = 0; jj < TT; jj++)
        E[jj] = lk ? __expf(trans_sh[jj * TT + k]) : 0.f;

    float npart = 0.f;
    for (int l = k; l < BB; l += 32) {
        int yl = yrow[l];
        npart += em_base[l * TT + yl];
        if (l + 1 < BB) npart += trans_sh[yl * TT + yrow[l + 1]];
    }
    if (k == 0) npart += start_tr[yrow[0]] + end_tr[yrow[BB - 1]];
#pragma unroll
    for (int off = 16; off; off >>= 1)
        npart += __shfl_xor_sync(FULL, npart, off);
    const float num = npart;

    float p    = lk ? __expf(start_tr[k] + em_base[k]) : 0.f;
    float logC = 0.f;

    for (int l = 1; l < BB; l++) {
        float s0 = 0.f, s1 = 0.f, s2 = 0.f, s3 = 0.f;
#pragma unroll
        for (int jj = 0; jj < 5; jj++) {
            float pj = __shfl_sync(FULL, p, jj);
            s0 = fmaf(pj, E[jj], s0);
        }
#pragma unroll
        for (int jj = 5; jj < 10; jj++) {
            float pj = __shfl_sync(FULL, p, jj);
            s1 = fmaf(pj, E[jj], s1);
        }
#pragma unroll
        for (int jj = 10; jj < 15; jj++) {
            float pj = __shfl_sync(FULL, p, jj);
            s2 = fmaf(pj, E[jj], s2);
        }
#pragma unroll
        for (int jj = 15; jj < 19; jj++) {
            float pj = __shfl_sync(FULL, p, jj);
            s3 = fmaf(pj, E[jj], s3);
        }
        float d = (s0 + s1) + (s2 + s3);
        float z = lk ? e_em[l][k] * d : 0.f;

        if ((l & 3) == 0) {
            float mz = __shfl_sync(FULL, z, 0);
            float r;
            asm("rcp.approx.f32 %0, %1;" : "=f"(r) : "f"(mz));
            p = z * r;
            logC += __logf(mz);
        } else {
            p = z;
        }
    }

    float term = lk ? p * __expf(end_tr[k]) : 0.f;
#pragma unroll
    for (int off = 16; off; off >>= 1)
        term += __shfl_xor_sync(FULL, term, off);
    float den = logC + __logf(term);

    if (k == 0) g_res[n] = num - den;
}

// ---------------------------------------------------------------------------
// K5: deterministic final reduce
// ---------------------------------------------------------------------------
__global__ void reduce_kernel(float* __restrict__ out)
{
    __shared__ float buf[512];
    int tid = threadIdx.x;
    buf[tid] = g_res[tid];
    __syncthreads();
    for (int s = 256; s > 0; s >>= 1) {
        if (tid < s) buf[tid] += buf[tid + s];
        __syncthreads();
    }
    if (tid == 0) out[0] = buf[0];
}

// ---------------------------------------------------------------------------
extern "C" void kernel_launch(void* const* d_in, const int* in_sizes, int n_in,
                              void* d_out, int out_size)
{
    const float* x        = (const float*)d_in[0];
    const int*   y        = (const int*)d_in[1];
    const float* W_ih_f   = (const float*)d_in[2];
    const float* W_hh_f   = (const float*)d_in[3];
    const float* b_ih_f   = (const float*)d_in[4];
    const float* b_hh_f   = (const float*)d_in[5];
    const float* W_ih_b   = (const float*)d_in[6];
    const float* W_hh_b   = (const float*)d_in[7];
    const float* b_ih_b   = (const float*)d_in[8];
    const float* b_hh_b   = (const float*)d_in[9];
    const float* W_tag    = (const float*)d_in[10];
    const float* b_tag    = (const float*)d_in[11];
    const float* start_tr = (const float*)d_in[12];
    const float* end_tr   = (const float*)d_in[13];
    const float* trans    = (const float*)d_in[14];
    float*       out      = (float*)d_out;

    const int logits_smem = (3800 + 128 * 202) * 4;   // 118624 B
    cudaFuncSetAttribute(proj_mma_kernel,
                         cudaFuncAttributeMaxDynamicSharedMemorySize, K1_SMEM);
    cudaFuncSetAttribute(rnn_scan_mma_kernel,
                         cudaFuncAttributeMaxDynamicSharedMemorySize, K2_SMEM);
    cudaFuncSetAttribute(logits_softmax_kernel,
                         cudaFuncAttributeMaxDynamicSharedMemorySize, logits_smem);

    proj_mma_kernel<<<MM / 128, 256, K1_SMEM>>>(
        x, W_ih_f, W_ih_b, b_ih_f, b_hh_f, b_ih_b, b_hh_b);

    rnn_scan_mma_kernel<<<dim3(BB / 16, 2), 256, K2_SMEM>>>(W_hh_f, W_hh_b);

    logits_softmax_kernel<<<MM / 128, 128, logits_smem>>>(W_tag, b_tag);

    crf_kernel<<<SS, 32>>>(y, start_tr, end_tr, trans);

    reduce_kernel<<<1, 512>>>(out);
}

// round 11
// speedup vs baseline: 3.1945x; 1.3210x over previous
#include <cuda_runtime.h>
#include <cuda_bf16.h>
#include <cstdint>

// Problem constants
#define SS   512
#define BB   256
#define DIN  202
#define HH   100
#define TT   19
#define MM   (SS*BB)   // 131072

// ---------------- scratch (device globals; no allocations allowed) ----------
__device__ uint32_t g_xp_bf[2ll * SS * BB * 50];   // bf16x2-packed xp
__device__ uint32_t g_h_pk[2ll * SS * BB * 50];    // bf16x2-packed hidden
__device__ float g_probs[(long long)SS * BB * TT]; // softmax emissions
__device__ float g_res[SS];                        // per-sequence CRF llh
__device__ __align__(16) uint32_t g_wih_img[224 * 108];  // bf16 W_ih image (K1 B)
__device__ __align__(16) uint32_t g_wtag_img[24 * 108];  // bf16 W_tag image (K3 B)

// ---------------- helpers ----------
typedef unsigned long long u64;

__device__ __forceinline__ uint32_t smem_u32(const void* p) {
    uint32_t a;
    asm("{ .reg .u64 t; cvta.to.shared.u64 t, %1; cvt.u32.u64 %0, t; }"
        : "=r"(a) : "l"(p));
    return a;
}
__device__ __forceinline__ uint32_t bf16x2(float lo, float hi) {
    uint32_t l = (uint32_t)__bfloat16_as_ushort(__float2bfloat16_rn(lo));
    uint32_t h = (uint32_t)__bfloat16_as_ushort(__float2bfloat16_rn(hi));
    return l | (h << 16);
}
__device__ __forceinline__ uint32_t bfpack2(float lo, float hi) {
    uint32_t r;
    asm("cvt.rn.bf16x2.f32 %0, %1, %2;" : "=r"(r) : "f"(hi), "f"(lo));
    return r;
}
__device__ __forceinline__ float bflo(uint32_t u) {
    return __uint_as_float(u << 16);
}
__device__ __forceinline__ float bfhi(uint32_t u) {
    return __uint_as_float(u & 0xffff0000u);
}

__device__ __forceinline__ void ldsm_x4(uint32_t a[4], uint32_t addr) {
    asm volatile("ldmatrix.sync.aligned.m8n8.x4.shared.b16 {%0,%1,%2,%3}, [%4];"
                 : "=r"(a[0]), "=r"(a[1]), "=r"(a[2]), "=r"(a[3]) : "r"(addr));
}
__device__ __forceinline__ void ldsm_x2(uint32_t a[2], uint32_t addr) {
    asm volatile("ldmatrix.sync.aligned.m8n8.x2.shared.b16 {%0,%1}, [%2];"
                 : "=r"(a[0]), "=r"(a[1]) : "r"(addr));
}
__device__ __forceinline__ void mma_bf16(float c[4], const uint32_t a[4],
                                         uint32_t b0, uint32_t b1) {
    asm volatile("mma.sync.aligned.m16n8k16.row.col.f32.bf16.bf16.f32 "
                 "{%0,%1,%2,%3}, {%4,%5,%6,%7}, {%8,%9}, {%0,%1,%2,%3};"
                 : "+f"(c[0]), "+f"(c[1]), "+f"(c[2]), "+f"(c[3])
                 : "r"(a[0]), "r"(a[1]), "r"(a[2]), "r"(a[3]),
                   "r"(b0), "r"(b1));
}
__device__ __forceinline__ void cp_async16(uint32_t dst, const void* src) {
    asm volatile("cp.async.cg.shared.global [%0], [%1], 16;"
                 :: "r"(dst), "l"(src) : "memory");
}
__device__ __forceinline__ void cp_async8(uint32_t dst, const void* src) {
    asm volatile("cp.async.ca.shared.global [%0], [%1], 8;"
                 :: "r"(dst), "l"(src) : "memory");
}

// ---------------------------------------------------------------------------
// K0 (prep): convert W_ih (both dirs) + W_tag to bf16 SMEM-image layouts.
// g_wih_img: 224 rows (0-111 Wf pad, 112-223 Wb pad) x 108 u32 (216 bf16).
// g_wtag_img: 24 rows (19 real) x 108 u32.
// ---------------------------------------------------------------------------
__global__ void prep_kernel(const float* __restrict__ Wf,
                            const float* __restrict__ Wb,
                            const float* __restrict__ Wtag)
{
    int i = blockIdx.x * 256 + threadIdx.x;
    if (i < 224 * 108) {
        int j = i / 108, kp = i - j * 108, k = 2 * kp;
        int d = j >= 112, jj = j - d * 112;
        const float* W = d ? Wb : Wf;
        float w0 = 0.f, w1 = 0.f;
        if (jj < HH) {
            if (k < DIN)     w0 = W[jj * DIN + k];
            if (k + 1 < DIN) w1 = W[jj * DIN + k + 1];
        }
        g_wih_img[i] = bf16x2(w0, w1);
    } else if (i < 224 * 108 + 24 * 108) {
        int i2 = i - 224 * 108;
        int t = i2 / 108, kp = i2 - t * 108, k = 2 * kp;
        float w0 = 0.f, w1 = 0.f;
        if (t < TT) {
            if (k < 200)     w0 = Wtag[t * 200 + k];
            if (k + 1 < 200) w1 = Wtag[t * 200 + k + 1];
        }
        g_wtag_img[i2] = bf16x2(w0, w1);
    }
}

// ---------------------------------------------------------------------------
// K1 (mma.sync bf16, BOTH dirs fused): B-fill now pure cp.async from image.
// ---------------------------------------------------------------------------
#define K1_STRIDE 216
#define K1_A_BYTES (128 * K1_STRIDE * 2)
#define K1_B_BYTES (224 * K1_STRIDE * 2)
#define K1_BIAS_OFF (K1_A_BYTES + K1_B_BYTES)
#define K1_SMEM (K1_BIAS_OFF + 208 * 4)

__global__ void proj_mma_kernel(const float* __restrict__ x,
                                const float* __restrict__ bihf,
                                const float* __restrict__ bhhf,
                                const float* __restrict__ bihb,
                                const float* __restrict__ bhhb)
{
    extern __shared__ __align__(16) char smem[];
    const uint32_t sbase = smem_u32(smem);
    float* bias_sh = (float*)(smem + K1_BIAS_OFF);

    const int tid = threadIdx.x;
    const int wid = tid >> 5;
    const int lane = tid & 31;
    const int r0  = blockIdx.x * 128;

    // B fill: straight 16B async copies of the prepped image (96768 B)
    {
        const uint32_t sB = sbase + K1_A_BYTES;
        const char* src = (const char*)g_wih_img;
        for (int idx = tid; idx < 6048; idx += 256)
            cp_async16(sB + idx * 16, src + idx * 16);
    }

    if (tid < 208) {
        int d = tid >= 104, jj = tid - d * 104;
        const float* bi = d ? bihb : bihf;
        const float* bh = d ? bhhb : bhhf;
        bias_sh[tid] = (jj < HH) ? (bi[jj] + bh[jj]) : 0.f;
    }

    // A fill: x tile with f32->bf16 conversion (reads x once)
    for (int idx = tid; idx < 128 * 104; idx += 256) {
        int r = idx / 104, kp = idx - r * 104, k = kp * 2;
        float2 xv = make_float2(0.f, 0.f);
        if (k < DIN) xv = *(const float2*)&x[(size_t)(r0 + r) * DIN + k];
        *(uint32_t*)(smem + r * 432 + kp * 4) = bf16x2(xv.x, xv.y);
    }
    asm volatile("cp.async.commit_group;" ::: "memory");
    asm volatile("cp.async.wait_group 0;" ::: "memory");
    __syncthreads();

    const int m0 = wid * 16;
    float accA[13][4], accB[13][4];
#pragma unroll
    for (int nt = 0; nt < 13; nt++)
#pragma unroll
        for (int c = 0; c < 4; c++) { accA[nt][c] = 0.f; accB[nt][c] = 0.f; }

    const uint32_t sA = sbase;
    const uint32_t sB = sbase + K1_A_BYTES;

    for (int kt = 0; kt < 13; kt++) {
        uint32_t a[4];
        ldsm_x4(a, sA + (uint32_t)((m0 + (lane & 15)) * 432 + kt * 32
                                   + (lane >> 4) * 16));
#pragma unroll
        for (int ntp = 0; ntp < 6; ntp++) {
            uint32_t b[4];
            int tile = 2 * ntp + (lane >> 4);
            ldsm_x4(b, sB + (uint32_t)((tile * 8 + (lane & 7)) * 432 + kt * 32
                                       + ((lane >> 3) & 1) * 16));
            mma_bf16(accA[2 * ntp],     a, b[0], b[1]);
            mma_bf16(accA[2 * ntp + 1], a, b[2], b[3]);
            ldsm_x4(b, sB + (uint32_t)(((112 + tile * 8) + (lane & 7)) * 432
                                       + kt * 32 + ((lane >> 3) & 1) * 16));
            mma_bf16(accB[2 * ntp],     a, b[0], b[1]);
            mma_bf16(accB[2 * ntp + 1], a, b[2], b[3]);
        }
        {
            uint32_t b[2];
            ldsm_x2(b, sB + (uint32_t)((96 + (lane & 7)) * 432 + kt * 32
                                       + ((lane >> 3) & 1) * 16));
            mma_bf16(accA[12], a, b[0], b[1]);
            ldsm_x2(b, sB + (uint32_t)((208 + (lane & 7)) * 432 + kt * 32
                                       + ((lane >> 3) & 1) * 16));
            mma_bf16(accB[12], a, b[0], b[1]);
        }
    }

    const int rowA = r0 + m0 + (lane >> 2);
    const int rowB = rowA + 8;
    uint32_t* d0A = &g_xp_bf[(size_t)rowA * 50];
    uint32_t* d0B = &g_xp_bf[(size_t)rowB * 50];
    uint32_t* d1A = &g_xp_bf[(size_t)MM * 50 + (size_t)rowA * 50];
    uint32_t* d1B = &g_xp_bf[(size_t)MM * 50 + (size_t)rowB * 50];
#pragma unroll
    for (int nt = 0; nt < 13; nt++) {
        int col = nt * 8 + (lane & 3) * 2;
        if (col < HH) {
            float b00 = bias_sh[col], b01 = bias_sh[col + 1];
            float b10 = bias_sh[104 + col], b11 = bias_sh[104 + col + 1];
            d0A[col >> 1] = bf16x2(accA[nt][0] + b00, accA[nt][1] + b01);
            d0B[col >> 1] = bf16x2(accA[nt][2] + b00, accA[nt][3] + b01);
            d1A[col >> 1] = bf16x2(accB[nt][0] + b10, accB[nt][1] + b11);
            d1B[col >> 1] = bf16x2(accB[nt][2] + b10, accB[nt][3] + b11);
        }
    }
}

// ---------------------------------------------------------------------------
// K2 (mma.sync recurrent scan) — unchanged from R10 (passing).
// ---------------------------------------------------------------------------
#define K2_STRIDE 240
#define K2_OFF_B 0
#define K2_OFF_A 24960
#define K2_OFF_X 32640
#define K2_SMEM  (32640 + 51200)

__global__ void __launch_bounds__(256)
rnn_scan_mma_kernel(const float* __restrict__ Whf,
                    const float* __restrict__ Whb)
{
    extern __shared__ __align__(16) char sm2[];
    const uint32_t sbase = smem_u32(sm2);
    uint32_t* xs = (uint32_t*)(sm2 + K2_OFF_X);

    const int tid  = threadIdx.x;
    const int w    = tid >> 5;
    const int lane = tid & 31;
    const int dir  = blockIdx.y;
    const int b0   = blockIdx.x * 16;
    const float* Whh = dir ? Whb : Whf;

    for (int idx = tid; idx < 104 * 60; idx += 256) {
        int j = idx / 60, kp = idx - j * 60, k = kp * 2;
        float w0 = 0.f, w1 = 0.f;
        if (j < HH && k < HH) { w0 = Whh[j * HH + k]; w1 = Whh[j * HH + k + 1]; }
        *(uint32_t*)(sm2 + K2_OFF_B + j * K2_STRIDE + kp * 4) = bf16x2(w0, w1);
    }
    for (int idx = tid; idx < 1920; idx += 256)
        ((uint32_t*)(sm2 + K2_OFF_A))[idx] = 0u;

    const uint32_t* xpg = g_xp_bf + (size_t)dir * SS * BB * 50;
    const int base = dir ? (SS - 1) : 0;
    const int sgn  = dir ? -1 : 1;
    for (int q = 0; q < 8; q++) {
        const uint32_t* src = xpg + (size_t)(base + sgn * q) * (BB * 50) + b0 * 50;
        for (int idx = tid; idx < 800; idx += 256)
            xs[q * 800 + idx] = src[idx];
    }
    __syncthreads();

    uint32_t Bf[7][4];
    if (w < 6) {
#pragma unroll
        for (int kt = 0; kt < 7; kt++)
            ldsm_x4(Bf[kt], sbase + K2_OFF_B
                    + (uint32_t)(((2 * w + (lane >> 4)) * 8 + (lane & 7)) * K2_STRIDE
                                 + kt * 32 + ((lane >> 3) & 1) * 16));
    } else if (w == 6) {
#pragma unroll
        for (int kt = 0; kt < 7; kt++)
            ldsm_x2(Bf[kt], sbase + K2_OFF_B
                    + (uint32_t)((96 + (lane & 7)) * K2_STRIDE
                                 + kt * 32 + ((lane >> 3) & 1) * 16));
    }

    const int rowA = lane >> 2;
    const int rowB = rowA + 8;

    for (int t0 = 0; t0 < SS; t0 += 8) {
        const int buf = (t0 >> 3) & 1;

        if (t0 + 8 < SS && tid < 200) {
#pragma unroll
            for (int q = 0; q < 8; q++) {
                const char* src = (const char*)(xpg
                    + (size_t)(base + sgn * (t0 + 8 + q)) * (BB * 50) + b0 * 50);
                cp_async16(sbase + K2_OFF_X + (buf ^ 1) * 25600 + q * 3200
                           + tid * 16, src + tid * 16);
            }
        }
        asm volatile("cp.async.commit_group;" ::: "memory");

        for (int it = 0; it < 8; it++) {
            const int t = t0 + it;
            const int cur = t & 1, nxt = cur ^ 1;

            if (w < 7) {
                float c0e[4] = {0,0,0,0}, c0o[4] = {0,0,0,0};
                float c1e[4] = {0,0,0,0}, c1o[4] = {0,0,0,0};
#pragma unroll
                for (int kt = 0; kt < 7; kt++) {
                    uint32_t a[4];
                    ldsm_x4(a, sbase + K2_OFF_A
                            + (uint32_t)(cur * 3840 + (lane & 15) * K2_STRIDE
                                         + kt * 32 + (lane >> 4) * 16));
                    float* c0 = (kt & 1) ? c0o : c0e;
                    mma_bf16(c0, a, Bf[kt][0], Bf[kt][1]);
                    if (w < 6) {
                        float* c1 = (kt & 1) ? c1o : c1e;
                        mma_bf16(c1, a, Bf[kt][2], Bf[kt][3]);
                    }
                }
                const int s = base + sgn * t;
                const uint32_t* xrow = &xs[buf * 6400 + it * 800];
                const size_t gb = ((size_t)dir * SS + s) * (BB * 50);

                {
                    int nt = (w < 6) ? 2 * w : 12;
                    int col = nt * 8 + (lane & 3) * 2;
                    uint32_t pA = xrow[rowA * 50 + (col >> 1)];
                    uint32_t pB = xrow[rowB * 50 + (col >> 1)];
                    float z0 = c0e[0] + c0o[0] + bflo(pA);
                    float z1 = c0e[1] + c0o[1] + bfhi(pA);
                    float z2 = c0e[2] + c0o[2] + bflo(pB);
                    float z3 = c0e[3] + c0o[3] + bfhi(pB);
                    float h0, h1, h2, h3;
                    asm("tanh.approx.f32 %0, %1;" : "=f"(h0) : "f"(z0));
                    asm("tanh.approx.f32 %0, %1;" : "=f"(h1) : "f"(z1));
                    asm("tanh.approx.f32 %0, %1;" : "=f"(h2) : "f"(z2));
                    asm("tanh.approx.f32 %0, %1;" : "=f"(h3) : "f"(z3));
                    uint32_t hA = bfpack2(h0, h1), hB = bfpack2(h2, h3);
                    if (col < HH) {
                        *(uint32_t*)(sm2 + K2_OFF_A + nxt * 3840
                                     + rowA * K2_STRIDE + col * 2) = hA;
                        *(uint32_t*)(sm2 + K2_OFF_A + nxt * 3840
                                     + rowB * K2_STRIDE + col * 2) = hB;
                        g_h_pk[gb + (b0 + rowA) * 50 + (col >> 1)] = hA;
                        g_h_pk[gb + (b0 + rowB) * 50 + (col >> 1)] = hB;
                    }
                }
                if (w < 6) {
                    int col = (2 * w + 1) * 8 + (lane & 3) * 2;
                    uint32_t pA = xrow[rowA * 50 + (col >> 1)];
                    uint32_t pB = xrow[rowB * 50 + (col >> 1)];
                    float z0 = c1e[0] + c1o[0] + bflo(pA);
                    float z1 = c1e[1] + c1o[1] + bfhi(pA);
                    float z2 = c1e[2] + c1o[2] + bflo(pB);
                    float z3 = c1e[3] + c1o[3] + bfhi(pB);
                    float h0, h1, h2, h3;
                    asm("tanh.approx.f32 %0, %1;" : "=f"(h0) : "f"(z0));
                    asm("tanh.approx.f32 %0, %1;" : "=f"(h1) : "f"(z1));
                    asm("tanh.approx.f32 %0, %1;" : "=f"(h2) : "f"(z2));
                    asm("tanh.approx.f32 %0, %1;" : "=f"(h3) : "f"(z3));
                    uint32_t hA = bfpack2(h0, h1), hB = bfpack2(h2, h3);
                    *(uint32_t*)(sm2 + K2_OFF_A + nxt * 3840
                                 + rowA * K2_STRIDE + col * 2) = hA;
                    *(uint32_t*)(sm2 + K2_OFF_A + nxt * 3840
                                 + rowB * K2_STRIDE + col * 2) = hB;
                    g_h_pk[gb + (b0 + rowA) * 50 + (col >> 1)] = hA;
                    g_h_pk[gb + (b0 + rowB) * 50 + (col >> 1)] = hB;
                }
            }
            if (it == 7)
                asm volatile("cp.async.wait_group 0;" ::: "memory");
            __syncthreads();
        }
    }
}

// ---------------------------------------------------------------------------
// K3 (mma.sync logits + in-fragment softmax):
// probs[128x19] per CTA. h tile [128][216 bf16] (fwd 0-99, bwd 100-199,
// pad 200-215 zero), stride 432 B. Wt from prepped image. 3 n-tiles (24 cols,
// pad logits = -1e30), 13 k-tiles. Softmax reduced over the 4-lane col group.
// ---------------------------------------------------------------------------
#define K3_H_BYTES (128 * 432)                  // 55296
#define K3_W_OFF   K3_H_BYTES
#define K3_BIAS_OFF (K3_H_BYTES + 24 * 432)     // 65664
#define K3_SMEM    (K3_BIAS_OFF + 128)

__global__ void __launch_bounds__(256)
logits_mma_kernel(const float* __restrict__ btag)
{
    extern __shared__ __align__(16) char sm3[];
    const uint32_t sbase = smem_u32(sm3);
    float* bias_sh = (float*)(sm3 + K3_BIAS_OFF);

    const int tid  = threadIdx.x;
    const int wid  = tid >> 5;
    const int lane = tid & 31;
    const int row0 = blockIdx.x * 128;

    if (tid < TT) bias_sh[tid] = btag[tid];

    // Wt fill (10368 B = 648 x 16B)
    {
        const char* src = (const char*)g_wtag_img;
        for (int idx = tid; idx < 648; idx += 256)
            cp_async16(sbase + K3_W_OFF + idx * 16, src + idx * 16);
    }
    // h fill: 8B async copies (fwd bytes 0-199, bwd 200-399 per row)
    const uint32_t* hf = g_h_pk;
    const uint32_t* hb = g_h_pk + (size_t)MM * 50;
    for (int idx = tid; idx < 128 * 25; idx += 256) {
        int r = idx / 25, c = idx - r * 25;
        cp_async8(sbase + r * 432 + c * 8,       hf + (size_t)(row0 + r) * 50 + c * 2);
        cp_async8(sbase + r * 432 + 200 + c * 8, hb + (size_t)(row0 + r) * 50 + c * 2);
    }
    // zero pad bytes 400-431 per row
    for (int idx = tid; idx < 128 * 8; idx += 256) {
        int r = idx >> 3, c = idx & 7;
        *(uint32_t*)(sm3 + r * 432 + 400 + c * 4) = 0u;
    }
    asm volatile("cp.async.commit_group;" ::: "memory");
    asm volatile("cp.async.wait_group 0;" ::: "memory");
    __syncthreads();

    const int m0 = wid * 16;
    float acc[3][4];
#pragma unroll
    for (int nt = 0; nt < 3; nt++)
#pragma unroll
        for (int c = 0; c < 4; c++) acc[nt][c] = 0.f;

    for (int kt = 0; kt < 13; kt++) {
        uint32_t a[4];
        ldsm_x4(a, sbase + (uint32_t)((m0 + (lane & 15)) * 432 + kt * 32
                                      + (lane >> 4) * 16));
        uint32_t b[4];
        ldsm_x4(b, sbase + K3_W_OFF
                + (uint32_t)(((lane >> 4) * 8 + (lane & 7)) * 432 + kt * 32
                             + ((lane >> 3) & 1) * 16));
        mma_bf16(acc[0], a, b[0], b[1]);
        mma_bf16(acc[1], a, b[2], b[3]);
        uint32_t b2[2];
        ldsm_x2(b2, sbase + K3_W_OFF
                + (uint32_t)((16 + (lane & 7)) * 432 + kt * 32
                             + ((lane >> 3) & 1) * 16));
        mma_bf16(acc[2], a, b2[0], b2[1]);
    }

    // ---- in-fragment softmax ----
    const unsigned FULL = 0xffffffffu;
    const int c0 = (lane & 3) * 2;
    float lgA[6], lgB[6];
#pragma unroll
    for (int nt = 0; nt < 3; nt++) {
        int col = nt * 8 + c0;
        lgA[2 * nt]     = (col < TT)     ? acc[nt][0] + bias_sh[col]     : -1e30f;
        lgA[2 * nt + 1] = (col + 1 < TT) ? acc[nt][1] + bias_sh[col + 1] : -1e30f;
        lgB[2 * nt]     = (col < TT)     ? acc[nt][2] + bias_sh[col]     : -1e30f;
        lgB[2 * nt + 1] = (col + 1 < TT) ? acc[nt][3] + bias_sh[col + 1] : -1e30f;
    }
    float mA = lgA[0], mB = lgB[0];
#pragma unroll
    for (int i = 1; i < 6; i++) { mA = fmaxf(mA, lgA[i]); mB = fmaxf(mB, lgB[i]); }
    mA = fmaxf(mA, __shfl_xor_sync(FULL, mA, 1));
    mA = fmaxf(mA, __shfl_xor_sync(FULL, mA, 2));
    mB = fmaxf(mB, __shfl_xor_sync(FULL, mB, 1));
    mB = fmaxf(mB, __shfl_xor_sync(FULL, mB, 2));
    float sA = 0.f, sB = 0.f;
#pragma unroll
    for (int i = 0; i < 6; i++) {
        lgA[i] = __expf(lgA[i] - mA); sA += lgA[i];
        lgB[i] = __expf(lgB[i] - mB); sB += lgB[i];
    }
    sA += __shfl_xor_sync(FULL, sA, 1);
    sA += __shfl_xor_sync(FULL, sA, 2);
    sB += __shfl_xor_sync(FULL, sB, 1);
    sB += __shfl_xor_sync(FULL, sB, 2);
    float iA = 1.0f / sA, iB = 1.0f / sB;

    const size_t rA = (size_t)(row0 + m0 + (lane >> 2)) * TT;
    const size_t rB = rA + 8 * TT;
#pragma unroll
    for (int nt = 0; nt < 3; nt++) {
        int col = nt * 8 + c0;
        if (col < TT)     { g_probs[rA + col]     = lgA[2 * nt] * iA;
                            g_probs[rB + col]     = lgB[2 * nt] * iB; }
        if (col + 1 < TT) { g_probs[rA + col + 1] = lgA[2 * nt + 1] * iA;
                            g_probs[rB + col + 1] = lgB[2 * nt + 1] * iB; }
    }
}

// ---------------------------------------------------------------------------
// K4: CRF llh (unchanged)
// ---------------------------------------------------------------------------
__global__ void __launch_bounds__(32)
crf_kernel(const int* __restrict__ y,
           const float* __restrict__ start_tr,
           const float* __restrict__ end_tr,
           const float* __restrict__ trans)
{
    __shared__ float trans_sh[TT * TT];
    __shared__ float e_em[BB][20];

    const int k = threadIdx.x;
    const int n = blockIdx.x;
    const bool lk = (k < TT);
    const unsigned FULL = 0xffffffffu;

    for (int idx = k; idx < TT * TT; idx += 32) trans_sh[idx] = trans[idx];

    const float* em_base = g_probs + (size_t)n * BB * TT;
    const int*   yrow    = y + (size_t)n * BB;

    for (int idx = k; idx < BB * TT; idx += 32) {
        int l = idx / TT, t = idx - l * TT;
        e_em[l][t] = __expf(em_base[idx]);
    }
    __syncwarp();

    float E[TT];
#pragma unroll
    for (int jj = 0; jj < TT; jj++)
        E[jj] = lk ? __expf(trans_sh[jj * TT + k]) : 0.f;

    float npart = 0.f;
    for (int l = k; l < BB; l += 32) {
        int yl = yrow[l];
        npart += em_base[l * TT + yl];
        if (l + 1 < BB) npart += trans_sh[yl * TT + yrow[l + 1]];
    }
    if (k == 0) npart += start_tr[yrow[0]] + end_tr[yrow[BB - 1]];
#pragma unroll
    for (int off = 16; off; off >>= 1)
        npart += __shfl_xor_sync(FULL, npart, off);
    const float num = npart;

    float p    = lk ? __expf(start_tr[k] + em_base[k]) : 0.f;
    float logC = 0.f;

    for (int l = 1; l < BB; l++) {
        float s0 = 0.f, s1 = 0.f, s2 = 0.f, s3 = 0.f;
#pragma unroll
        for (int jj = 0; jj < 5; jj++) {
            float pj = __shfl_sync(FULL, p, jj);
            s0 = fmaf(pj, E[jj], s0);
        }
#pragma unroll
        for (int jj = 5; jj < 10; jj++) {
            float pj = __shfl_sync(FULL, p, jj);
            s1 = fmaf(pj, E[jj], s1);
        }
#pragma unroll
        for (int jj = 10; jj < 15; jj++) {
            float pj = __shfl_sync(FULL, p, jj);
            s2 = fmaf(pj, E[jj], s2);
        }
#pragma unroll
        for (int jj = 15; jj < 19; jj++) {
            float pj = __shfl_sync(FULL, p, jj);
            s3 = fmaf(pj, E[jj], s3);
        }
        float d = (s0 + s1) + (s2 + s3);
        float z = lk ? e_em[l][k] * d : 0.f;

        if ((l & 3) == 0) {
            float mz = __shfl_sync(FULL, z, 0);
            float r;
            asm("rcp.approx.f32 %0, %1;" : "=f"(r) : "f"(mz));
            p = z * r;
            logC += __logf(mz);
        } else {
            p = z;
        }
    }

    float term = lk ? p * __expf(end_tr[k]) : 0.f;
#pragma unroll
    for (int off = 16; off; off >>= 1)
        term += __shfl_xor_sync(FULL, term, off);
    float den = logC + __logf(term);

    if (k == 0) g_res[n] = num - den;
}

// ---------------------------------------------------------------------------
// K5: deterministic final reduce
// ---------------------------------------------------------------------------
__global__ void reduce_kernel(float* __restrict__ out)
{
    __shared__ float buf[512];
    int tid = threadIdx.x;
    buf[tid] = g_res[tid];
    __syncthreads();
    for (int s = 256; s > 0; s >>= 1) {
        if (tid < s) buf[tid] += buf[tid + s];
        __syncthreads();
    }
    if (tid == 0) out[0] = buf[0];
}

// ---------------------------------------------------------------------------
extern "C" void kernel_launch(void* const* d_in, const int* in_sizes, int n_in,
                              void* d_out, int out_size)
{
    const float* x        = (const float*)d_in[0];
    const int*   y        = (const int*)d_in[1];
    const float* W_ih_f   = (const float*)d_in[2];
    const float* W_hh_f   = (const float*)d_in[3];
    const float* b_ih_f   = (const float*)d_in[4];
    const float* b_hh_f   = (const float*)d_in[5];
    const float* W_ih_b   = (const float*)d_in[6];
    const float* W_hh_b   = (const float*)d_in[7];
    const float* b_ih_b   = (const float*)d_in[8];
    const float* b_hh_b   = (const float*)d_in[9];
    const float* W_tag    = (const float*)d_in[10];
    const float* b_tag    = (const float*)d_in[11];
    const float* start_tr = (const float*)d_in[12];
    const float* end_tr   = (const float*)d_in[13];
    const float* trans    = (const float*)d_in[14];
    float*       out      = (float*)d_out;

    cudaFuncSetAttribute(proj_mma_kernel,
                         cudaFuncAttributeMaxDynamicSharedMemorySize, K1_SMEM);
    cudaFuncSetAttribute(rnn_scan_mma_kernel,
                         cudaFuncAttributeMaxDynamicSharedMemorySize, K2_SMEM);
    cudaFuncSetAttribute(logits_mma_kernel,
                         cudaFuncAttributeMaxDynamicSharedMemorySize, K3_SMEM);

    prep_kernel<<<105, 256>>>(W_ih_f, W_ih_b, W_tag);

    proj_mma_kernel<<<MM / 128, 256, K1_SMEM>>>(
        x, b_ih_f, b_hh_f, b_ih_b, b_hh_b);

    rnn_scan_mma_kernel<<<dim3(BB / 16, 2), 256, K2_SMEM>>>(W_hh_f, W_hh_b);

    logits_mma_kernel<<<MM / 128, 256, K3_SMEM>>>(b_tag);

    crf_kernel<<<SS, 32>>>(y, start_tr, end_tr, trans);

    reduce_kernel<<<1, 512>>>(out);
}